// round 15
// baseline (speedup 1.0000x reference)
#include <cuda_runtime.h>
#include <math.h>

#define N_NODES 8000
#define FDIM    128
#define EDGES   256000
#define C0      400
#define C1      20
#define ZSPLIT  25

// ---------------- static device scratch (no runtime allocation) ----------------
__device__ float g_xp0[N_NODES*FDIM];
__device__ float g_xp1[N_NODES*FDIM];
__device__ float g_hA [N_NODES*FDIM];
__device__ float g_hB1[N_NODES*FDIM];
__device__ float g_hB2[N_NODES*FDIM];
__device__ float g_S0 [N_NODES*C0];
__device__ float g_corr0[N_NODES*FDIM];
__device__ float g_cs0[C0];
__device__ float g_cs1[C1];
__device__ float g_xc1  [C0*FDIM];
__device__ float g_corr1[C0*FDIM];
__device__ float g_T0   [C0*FDIM];
__device__ float g_G0   [C0*FDIM];
__device__ float g_S1   [C0*C1];
__device__ float g_xc2  [C1*FDIM];
__device__ float g_corr2[C1*FDIM];
__device__ float g_T1   [C1*FDIM];
__device__ float g_G1   [C1*FDIM];
__device__ float g_P1   [N_NODES*C1];
__device__ float g_pa1[250*C0];
__device__ float g_pa2[250*C0];
__device__ float g_pc1[250*C0];
__device__ float g_csA[FDIM];
__device__ float g_cssA[FDIM];
__device__ float g_csB[FDIM];
__device__ float g_qB [FDIM];
__device__ float g_csC[FDIM];
__device__ float g_qC [FDIM];
__device__ float g_pb1[250*FDIM];
__device__ float g_pb2[250*FDIM];
__device__ float g_csX[FDIM];
__device__ float g_cssX[FDIM];
__device__ float g_tnpart [ZSPLIT*C0*FDIM];
__device__ float g_tnpart2[ZSPLIT*C0*FDIM];
__device__ float g_mB[(size_t)FDIM*EDGES];   // f-major [F][E] K=400 mask
__device__ int   g_cnt[N_NODES];
__device__ int   g_off[N_NODES+1];
__device__ int   g_cur[N_NODES];
__device__ int   g_colS[EDGES];
__device__ float g_wS  [EDGES];

// ---------------- zero all atomic-accumulated buffers + cnt (one launch) --------
__global__ void k_zero() {
    int i = blockIdx.x * blockDim.x + threadIdx.x;
    if (i < N_NODES) g_cnt[i] = 0;
    if (i < FDIM) { g_csB[i] = 0.f; g_qB[i] = 0.f; g_csC[i] = 0.f; g_qC[i] = 0.f; }
    if (i < C1) g_cs1[i] = 0.f;
}

// ---------------- two-stage deterministic column stats ----------------
__global__ void k_psum(const float* __restrict__ A, int n, int c, int rowsPer,
                       float* __restrict__ ps, float* __restrict__ pq) {
    int b = blockIdx.x;
    int r0 = b * rowsPer, r1 = min(n, r0 + rowsPer);
    for (int col = threadIdx.x; col < c; col += blockDim.x) {
        float s = 0.f, q = 0.f;
        for (int r = r0; r < r1; r++) {
            float v = A[(size_t)r * c + col];
            s += v; q += v * v;
        }
        ps[(size_t)b * c + col] = s;
        if (pq) pq[(size_t)b * c + col] = q;
    }
}

__global__ void k_preduce(const float* __restrict__ ps, const float* __restrict__ pq,
                          int nb, int c, int n,
                          float* __restrict__ outS, float* __restrict__ outCss) {
    int col = blockIdx.x * blockDim.x + threadIdx.x;
    if (col >= c) return;
    float s = 0.f, q = 0.f;
    for (int b = 0; b < nb; b++) {
        s += ps[(size_t)b * c + col];
        if (pq) q += pq[(size_t)b * c + col];
    }
    outS[col] = s;
    if (outCss) outCss[col] = q - s * s / (float)n;
}

// ---------------- node correlation (+ optional fused gains) ----------------
__global__ void k_corr(const float* __restrict__ z, int n,
                       const float* __restrict__ cs, const float* __restrict__ cssOrQ,
                       float* __restrict__ out,
                       const float* __restrict__ T, float* __restrict__ G, int rawq) {
    int r = blockIdx.x, f = threadIdx.x;
    float s = cs[f];
    float mean = s / (float)n;
    float css = rawq ? (cssOrQ[f] - s * s / (float)n) : cssOrQ[f];
    float inv = 1.f / (sqrtf(css) + 1e-12f);
    float v = (z[(size_t)r * FDIM + f] - mean) * inv;
    __shared__ float red[128];
    red[f] = v; __syncthreads();
    for (int st = 64; st > 0; st >>= 1) {
        if (f < st) red[f] += red[f + st];
        __syncthreads();
    }
    size_t idx = (size_t)r * FDIM + f;
    float cv = v * red[0];
    out[idx] = cv;
    if (T) {
        float x = 1.f / (1.f + expf(T[idx] - cv));
        G[idx] = x * x;
    }
}

// ---------------- softmax for S0 rows (W=400), register-resident ----------------
__global__ void k_softmax400(float* __restrict__ X) {
    int r = blockIdx.x;
    float* row = X + (size_t)r * C0;
    int t = threadIdx.x;
    int cnt = (t < C0 - 3 * 128) ? 4 : 3;
    float v[4];
    float m = -3.4e38f;
#pragma unroll
    for (int j = 0; j < 4; j++) {
        if (j < cnt) { v[j] = row[t + 128 * j]; m = fmaxf(m, v[j]); }
    }
    __shared__ float red[128];
    red[t] = m; __syncthreads();
    for (int s = 64; s > 0; s >>= 1) {
        if (t < s) red[t] = fmaxf(red[t], red[t + s]);
        __syncthreads();
    }
    m = red[0]; __syncthreads();
    float sum = 0.f;
#pragma unroll
    for (int j = 0; j < 4; j++) {
        if (j < cnt) { v[j] = expf(v[j] - m); sum += v[j]; }
    }
    red[t] = sum; __syncthreads();
    for (int s = 64; s > 0; s >>= 1) {
        if (t < s) red[t] += red[t + s];
        __syncthreads();
    }
    float inv = 1.f / red[0];
#pragma unroll
    for (int j = 0; j < 4; j++) {
        if (j < cnt) row[t + 128 * j] = v[j] * inv;
    }
}

// ---------------- softmax for S1 rows (W=20), warp/row + fused colsum ----------
__global__ void k_softmax20(float* __restrict__ X, float* __restrict__ cs) {
    int warp = (blockIdx.x * blockDim.x + threadIdx.x) >> 5;
    int lane = threadIdx.x & 31;
    if (warp >= C0) return;
    float* row = X + (size_t)warp * C1;
    float v = (lane < C1) ? row[lane] : -3.4e38f;
    float m = v;
#pragma unroll
    for (int o = 16; o; o >>= 1) m = fmaxf(m, __shfl_xor_sync(0xFFFFFFFFu, m, o));
    float e = (lane < C1) ? expf(v - m) : 0.f;
    float s = e;
#pragma unroll
    for (int o = 16; o; o >>= 1) s += __shfl_xor_sync(0xFFFFFFFFu, s, o);
    if (lane < C1) {
        float val = e / s;
        row[lane] = val;
        atomicAdd(&cs[lane], val);
    }
}

// ---------------- tf32 helper ----------------
__device__ __forceinline__ unsigned tf32r(float x) {
    unsigned u;
    asm("cvt.rna.tf32.f32 %0, %1;" : "=r"(u) : "f"(x));
    return u;
}

#define MMA_TF32(ACC, A0, A1, A2, A3, B0, B1)                                  \
    asm volatile(                                                              \
        "mma.sync.aligned.m16n8k8.row.col.f32.tf32.tf32.f32 "                  \
        "{%0,%1,%2,%3}, {%4,%5,%6,%7}, {%8,%9}, {%0,%1,%2,%3};"                \
        : "+f"(ACC[0]), "+f"(ACC[1]), "+f"(ACC[2]), "+f"(ACC[3])               \
        : "r"(A0), "r"(A1), "r"(A2), "r"(A3), "r"(B0), "r"(B1))

// ---------------- split-3 tf32 NN GEMM (fp32-accurate): C = act(A@B + bias) -----
__global__ void __launch_bounds__(256)
k_nn_mma3(int M, int N,
          const float* __restrict__ A, const float* __restrict__ B,
          const float* __restrict__ bias, float* __restrict__ C,
          int act, const float* __restrict__ aux) {
    extern __shared__ __align__(16) char sm3[];
    unsigned (*Ah)[36] = (unsigned(*)[36])(sm3);
    unsigned (*Al)[36] = (unsigned(*)[36])(sm3 + 18432);
    unsigned (*Bh)[72] = (unsigned(*)[72])(sm3 + 36864);
    unsigned (*Bl)[72] = (unsigned(*)[72])(sm3 + 46080);
    int t = threadIdx.x, lane = t & 31, w = t >> 5;
    int m0 = blockIdx.x * 128, n0 = blockIdx.y * 64;
    float acc[8][4];
#pragma unroll
    for (int nt = 0; nt < 8; nt++)
#pragma unroll
        for (int i = 0; i < 4; i++) acc[nt][i] = 0.f;

    for (int k0 = 0; k0 < 128; k0 += 32) {
        for (int idx = t; idx < 128 * 32; idx += 256) {
            int r = idx >> 5, kk = idx & 31;
            int row = m0 + r;
            float v = (row < M) ? A[(size_t)row * 128 + k0 + kk] : 0.f;
            unsigned h = tf32r(v);
            Ah[r][kk] = h;
            Al[r][kk] = tf32r(v - __uint_as_float(h));
        }
        for (int idx = t; idx < 32 * 64; idx += 256) {
            int kk = idx >> 6, n = idx & 63;
            int col = n0 + n;
            float v = (col < N) ? B[(size_t)(k0 + kk) * N + col] : 0.f;
            unsigned h = tf32r(v);
            Bh[kk][n] = h;
            Bl[kk][n] = tf32r(v - __uint_as_float(h));
        }
        __syncthreads();
#pragma unroll
        for (int ks = 0; ks < 4; ks++) {
            int kb = ks * 8;
            int ar = w * 16 + (lane >> 2);
            int ak = kb + (lane & 3);
            unsigned ah0 = Ah[ar][ak],     ah1 = Ah[ar + 8][ak];
            unsigned ah2 = Ah[ar][ak + 4], ah3 = Ah[ar + 8][ak + 4];
            unsigned al0 = Al[ar][ak],     al1 = Al[ar + 8][ak];
            unsigned al2 = Al[ar][ak + 4], al3 = Al[ar + 8][ak + 4];
#pragma unroll
            for (int nt = 0; nt < 8; nt++) {
                int bn = nt * 8 + (lane >> 2);
                unsigned bh0 = Bh[kb + (lane & 3)][bn];
                unsigned bh1 = Bh[kb + (lane & 3) + 4][bn];
                unsigned bl0 = Bl[kb + (lane & 3)][bn];
                unsigned bl1 = Bl[kb + (lane & 3) + 4][bn];
                MMA_TF32(acc[nt], ah0, ah1, ah2, ah3, bh0, bh1);
                MMA_TF32(acc[nt], ah0, ah1, ah2, ah3, bl0, bl1);
                MMA_TF32(acc[nt], al0, al1, al2, al3, bh0, bh1);
            }
        }
        __syncthreads();
    }
    float slope = (act == 2) ? aux[0] : 0.f;
    int rbase = m0 + w * 16 + (lane >> 2);
#pragma unroll
    for (int nt = 0; nt < 8; nt++) {
        int cb = n0 + nt * 8 + 2 * (lane & 3);
#pragma unroll
        for (int q = 0; q < 4; q++) {
            int r = rbase + ((q >= 2) ? 8 : 0);
            int c = cb + (q & 1);
            if (r < M && c < N) {
                float v = acc[nt][q];
                if (bias) v += bias[c];
                if (act == 1) v = fmaxf(v, 0.f);
                else if (act == 2) v = (v >= 0.f) ? v : slope * v;
                C[(size_t)r * N + c] = v;
            }
        }
    }
}

// ---------------- generic tiled SIMT GEMM (small uses) ----------------
__global__ void k_gemm_nn(int M, int N, int K,
                          const float* __restrict__ A, const float* __restrict__ B,
                          const float* __restrict__ bias, float* __restrict__ C,
                          int act, const float* __restrict__ aux) {
    __shared__ __align__(16) float As[16][68];
    __shared__ __align__(16) float Bs[16][64];
    int t = threadIdx.x;
    int m0 = blockIdx.x * 64, n0 = blockIdx.y * 64;
    int tx = t & 15, ty = t >> 4;
    float acc[4][4];
#pragma unroll
    for (int i = 0; i < 4; i++)
#pragma unroll
        for (int j = 0; j < 4; j++) acc[i][j] = 0.f;
    for (int k0 = 0; k0 < K; k0 += 16) {
        __syncthreads();
        for (int idx = t; idx < 1024; idx += 256) {
            int kk = idx & 15, r = idx >> 4;
            int row = m0 + r;
            As[kk][r] = (row < M) ? A[(size_t)row * K + k0 + kk] : 0.f;
        }
        for (int idx = t; idx < 1024; idx += 256) {
            int kk = idx >> 6, c = idx & 63;
            int col = n0 + c;
            Bs[kk][c] = (col < N) ? B[(size_t)(k0 + kk) * N + col] : 0.f;
        }
        __syncthreads();
#pragma unroll
        for (int kk = 0; kk < 16; kk++) {
            float4 av = *(const float4*)&As[kk][ty * 4];
            float4 bv = *(const float4*)&Bs[kk][tx * 4];
            float a4[4] = {av.x, av.y, av.z, av.w};
            float b4[4] = {bv.x, bv.y, bv.z, bv.w};
#pragma unroll
            for (int i = 0; i < 4; i++)
#pragma unroll
                for (int j = 0; j < 4; j++) acc[i][j] += a4[i] * b4[j];
        }
    }
    float slope = (act == 2) ? aux[0] : 0.f;
#pragma unroll
    for (int i = 0; i < 4; i++) {
        int row = m0 + ty * 4 + i;
        if (row >= M) continue;
#pragma unroll
        for (int j = 0; j < 4; j++) {
            int col = n0 + tx * 4 + j;
            if (col >= N) continue;
            float v = acc[i][j];
            if (bias) v += bias[col];
            if (act == 1) v = fmaxf(v, 0.f);
            else if (act == 2) v = (v >= 0.f) ? v : slope * v;
            C[(size_t)row * N + col] = v;
        }
    }
}

// ---------------- tf32 MMA TN GEMM (split-m) ----------------
__global__ void __launch_bounds__(256)
k_tn_mma(const float* __restrict__ A,
         const float* __restrict__ B1, const float* __restrict__ B2,
         float* __restrict__ part1, float* __restrict__ part2) {
    __shared__ unsigned As[64][33];
    __shared__ unsigned Bs1[32][136];
    __shared__ unsigned Bs2[32][136];
    int t = threadIdx.x, lane = t & 31, w = t >> 5;
    int wr = w & 3, wc = w >> 2;
    int k10 = blockIdx.x * 64;
    int mBase = blockIdx.y * 320;
    float acc1[8][4], acc2[8][4];
#pragma unroll
    for (int nt = 0; nt < 8; nt++)
#pragma unroll
        for (int i = 0; i < 4; i++) { acc1[nt][i] = 0.f; acc2[nt][i] = 0.f; }

    for (int mc = 0; mc < 320; mc += 32) {
        for (int idx = t; idx < 2048; idx += 256) {
            int m = idx >> 6, kl = idx & 63;
            int k1 = k10 + kl;
            float v = (k1 < C0) ? A[(size_t)(mBase + mc + m) * C0 + k1] : 0.f;
            As[kl][m] = tf32r(v);
        }
        for (int idx = t; idx < 4096; idx += 256) {
            int m = idx >> 7, n = idx & 127;
            size_t g = (size_t)(mBase + mc + m) * FDIM + n;
            Bs1[m][n] = tf32r(B1[g]);
            Bs2[m][n] = tf32r(B2[g]);
        }
        __syncthreads();
#pragma unroll
        for (int ks = 0; ks < 4; ks++) {
            int ar = wr * 16 + (lane >> 2);
            int ak = ks * 8 + (lane & 3);
            unsigned a0 = As[ar][ak];
            unsigned a1 = As[ar + 8][ak];
            unsigned a2 = As[ar][ak + 4];
            unsigned a3 = As[ar + 8][ak + 4];
#pragma unroll
            for (int nt = 0; nt < 8; nt++) {
                int bn = wc * 64 + nt * 8 + (lane >> 2);
                unsigned b0 = Bs1[ks * 8 + (lane & 3)][bn];
                unsigned b1 = Bs1[ks * 8 + (lane & 3) + 4][bn];
                MMA_TF32(acc1[nt], a0, a1, a2, a3, b0, b1);
                unsigned c0 = Bs2[ks * 8 + (lane & 3)][bn];
                unsigned c1 = Bs2[ks * 8 + (lane & 3) + 4][bn];
                MMA_TF32(acc2[nt], a0, a1, a2, a3, c0, c1);
            }
        }
        __syncthreads();
    }
    int z = blockIdx.y;
    int k1r = k10 + wr * 16 + (lane >> 2);
    int cb = 2 * (lane & 3);
#pragma unroll
    for (int nt = 0; nt < 8; nt++) {
        int n = wc * 64 + nt * 8 + cb;
        if (k1r < C0) {
            size_t b = ((size_t)z * C0 + k1r) * FDIM + n;
            part1[b] = acc1[nt][0]; part1[b + 1] = acc1[nt][1];
            part2[b] = acc2[nt][0]; part2[b + 1] = acc2[nt][1];
        }
        if (k1r + 8 < C0) {
            size_t b = ((size_t)z * C0 + k1r + 8) * FDIM + n;
            part1[b] = acc1[nt][2]; part1[b + 1] = acc1[nt][3];
            part2[b] = acc2[nt][2]; part2[b + 1] = acc2[nt][3];
        }
    }
}

// dual reduce + fused atomic column-stats of out1 (if csS!=0)
__global__ void k_tn_red2(const float* __restrict__ part1, const float* __restrict__ part2,
                          int S, int K1, int N,
                          const float* __restrict__ divrow,
                          float* __restrict__ out1, float* __restrict__ out2,
                          float* __restrict__ csS, float* __restrict__ qS) {
    int i = blockIdx.x * blockDim.x + threadIdx.x;
    if (i >= K1 * N) return;
    float s1 = 0.f, s2 = 0.f;
    for (int b = 0; b < S; b++) {
        s1 += part1[(size_t)b * K1 * N + i];
        s2 += part2[(size_t)b * K1 * N + i];
    }
    if (divrow) s1 /= (divrow[i / N] + 1e-12f);
    out1[i] = s1;
    out2[i] = s2;
    if (csS) {
        int f = i % N;
        atomicAdd(&csS[f], s1);
        atomicAdd(&qS[f], s1 * s1);
    }
}

// ---------------- fused level-1 TN: xc2 = S1^T@xc1/cs1, T1 = S1^T@corr1 ----------
__global__ void k_tn16(const float* __restrict__ S1,
                       const float* __restrict__ B1, const float* __restrict__ B2,
                       const float* __restrict__ cs1,
                       float* __restrict__ out1, float* __restrict__ out2,
                       float* __restrict__ csS, float* __restrict__ qS) {
    int k1 = blockIdx.x, f = threadIdx.x;
    float a1 = 0.f, a2 = 0.f;
    for (int m = 0; m < C0; m++) {
        float s = S1[m * C1 + k1];
        a1 += s * B1[(size_t)m * FDIM + f];
        a2 += s * B2[(size_t)m * FDIM + f];
    }
    float o1 = a1 / (cs1[k1] + 1e-12f);
    out1[(size_t)k1 * FDIM + f] = o1;
    out2[(size_t)k1 * FDIM + f] = a2;
    atomicAdd(&csS[f], o1);
    atomicAdd(&qS[f], o1 * o1);
}

// ---------------- mask MMA writer: mB[f][e] = sum_k S0[r,k]S0[c,k]G0sq[k,f] -------
// smem 67072 B: Us[128][36]@0 (alias Ms), Gs[32][136]@18432, rr@66048, cc@66560
__global__ void __launch_bounds__(256, 2)
k_mask_w(const float* __restrict__ s0p, const float* __restrict__ g0sq,
         const int* __restrict__ er, const int* __restrict__ ec,
         float* __restrict__ outMb) {
    extern __shared__ __align__(16) char sm[];
    unsigned (*Us)[36]  = (unsigned(*)[36])(sm);
    unsigned (*Gs)[136] = (unsigned(*)[136])(sm + 18432);
    float (*Ms)[129]    = (float(*)[129])(sm);
    int* rr             = (int*)(sm + 66048);
    int* cc             = (int*)(sm + 66560);

    int t = threadIdx.x, lane = t & 31, w = t >> 5;
    int e0 = blockIdx.x * 128;
    if (t < 128) { rr[t] = er[e0 + t]; cc[t] = ec[e0 + t]; }
    float acc[16][4];
#pragma unroll
    for (int nt = 0; nt < 16; nt++)
#pragma unroll
        for (int i = 0; i < 4; i++) acc[nt][i] = 0.f;
    __syncthreads();

    for (int k0 = 0; k0 < C0; k0 += 32) {
        for (int idx = t; idx < 32 * 128; idx += 256) {
            int kk = idx >> 7, f = idx & 127;
            float v = (k0 + kk < C0) ? g0sq[(size_t)(k0 + kk) * FDIM + f] : 0.f;
            Gs[kk][f] = tf32r(v);
        }
        for (int idx = t; idx < 128 * 32; idx += 256) {
            int kk = idx & 31, e = idx >> 5;
            float v = 0.f;
            if (k0 + kk < C0)
                v = s0p[(size_t)rr[e] * C0 + k0 + kk] * s0p[(size_t)cc[e] * C0 + k0 + kk];
            Us[e][kk] = tf32r(v);
        }
        __syncthreads();
#pragma unroll
        for (int ks = 0; ks < 4; ks++) {
            int kb = ks * 8;
            int ar = w * 16 + (lane >> 2);
            int ak = kb + (lane & 3);
            unsigned a0 = Us[ar][ak];
            unsigned a1 = Us[ar + 8][ak];
            unsigned a2 = Us[ar][ak + 4];
            unsigned a3 = Us[ar + 8][ak + 4];
#pragma unroll
            for (int nt = 0; nt < 16; nt++) {
                int bn = nt * 8 + (lane >> 2);
                unsigned b0 = Gs[kb + (lane & 3)][bn];
                unsigned b1 = Gs[kb + (lane & 3) + 4][bn];
                MMA_TF32(acc[nt], a0, a1, a2, a3, b0, b1);
            }
        }
        __syncthreads();
    }
    {
        int r = w * 16 + (lane >> 2);
        int cb = 2 * (lane & 3);
#pragma unroll
        for (int nt = 0; nt < 16; nt++) {
            int c = nt * 8 + cb;
            Ms[c][r]         = acc[nt][0];
            Ms[c + 1][r]     = acc[nt][1];
            Ms[c][r + 8]     = acc[nt][2];
            Ms[c + 1][r + 8] = acc[nt][3];
        }
    }
    __syncthreads();
    for (int idx = t; idx < 128 * 128; idx += 256) {
        int f = idx >> 7, e = idx & 127;
        outMb[(size_t)f * EDGES + e0 + e] = Ms[f][e];
    }
}

// ---------------- carry: thread per edge, mA on the fly, mB from gmem ----------
__global__ void k_carry_g(const float* __restrict__ p1, const float* __restrict__ g1sq,
                          const int* __restrict__ er, const int* __restrict__ ec,
                          const float* __restrict__ adjv, const float* __restrict__ mB,
                          float* __restrict__ outAdj) {
    __shared__ float G1s[C1][FDIM];
    int t = threadIdx.x;
    for (int idx = t; idx < C1 * FDIM; idx += 256)
        G1s[idx >> 7][idx & 127] = g1sq[idx];
    __syncthreads();
    int e = blockIdx.x * 256 + t;
    float u20[C1];
    const float* pr = p1 + (size_t)er[e] * C1;
    const float* pc = p1 + (size_t)ec[e] * C1;
#pragma unroll
    for (int k = 0; k < C1; k++) u20[k] = pr[k] * pc[k];
    float a = adjv[e];
    for (int f = 0; f < FDIM; f++) {
        float mA = 0.f;
#pragma unroll
        for (int k = 0; k < C1; k++) mA += u20[k] * G1s[k][f];
        float mBv = mB[(size_t)f * EDGES + e];
        float tq = a * mA;
        outAdj[(size_t)f * EDGES + e] = tq + tq * mBv;
        a = tq * mBv;
    }
}

// ---------------- CSR build ----------------
__global__ void k_count(const int* __restrict__ er) {
    int e = blockIdx.x * blockDim.x + threadIdx.x;
    if (e < EDGES) atomicAdd(&g_cnt[er[e]], 1);
}

__global__ void k_scan() {
    __shared__ int part[1024];
    const int n = N_NODES;
    const int per = (n + 1023) / 1024;
    int t = threadIdx.x;
    int s = 0;
    int lo = t * per, hi = min(n, (t + 1) * per);
    for (int i = lo; i < hi; i++) s += g_cnt[i];
    part[t] = s; __syncthreads();
    for (int off = 1; off < 1024; off <<= 1) {
        int v = (t >= off) ? part[t - off] : 0;
        __syncthreads();
        part[t] += v;
        __syncthreads();
    }
    int base = (t == 0) ? 0 : part[t - 1];
    for (int i = lo; i < hi; i++) {
        g_off[i] = base; g_cur[i] = base; base += g_cnt[i];
    }
    if (t == 1023) g_off[n] = base;
}

__global__ void k_scatter(const int* __restrict__ er, const int* __restrict__ ec,
                          const float* __restrict__ nv) {
    int e = blockIdx.x * blockDim.x + threadIdx.x;
    if (e < EDGES) {
        int pos = atomicAdd(&g_cur[er[e]], 1);
        g_colS[pos] = ec[e];
        g_wS[pos]   = nv[e];
    }
}

// ---------------- propagation step with fused BN on gathered input ----------------
__global__ void k_prop_bn(const float* __restrict__ x,
                          const float* __restrict__ cs, const float* __restrict__ css,
                          const float* __restrict__ gam, const float* __restrict__ bet,
                          float* __restrict__ xout) {
    int r = blockIdx.x * 2 + (threadIdx.x >> 7);
    int f = threadIdx.x & 127;
    float mu   = cs[f]  * (1.f / N_NODES);
    float var  = css[f] * (1.f / N_NODES);
    float rstd = rsqrtf(var + 1e-5f);
    float scale = gam[f] * rstd;
    float shift = bet[f] - mu * scale;
    float acc = 0.f;
    int s = g_off[r], e = g_off[r + 1];
    for (int i = s; i < e; i++) {
        int c = g_colS[i];
        float w = g_wS[i];
        acc += w * (x[(size_t)c * FDIM + f] * scale + shift);
    }
    xout[(size_t)r * FDIM + f] = acc;
}

// ---------------- plain propagation step (2 nodes per block) ----------------
__global__ void k_prop(const float* __restrict__ xin, float* __restrict__ xout) {
    int r = blockIdx.x * 2 + (threadIdx.x >> 7);
    int f = threadIdx.x & 127;
    float acc = 0.f;
    int s = g_off[r], e = g_off[r + 1];
    for (int i = s; i < e; i++) {
        int c = g_colS[i];
        float w = g_wS[i];
        acc += w * xin[(size_t)c * FDIM + f];
    }
    xout[(size_t)r * FDIM + f] = acc;
}

// ---------------- final logits + log_softmax ----------------
__global__ void k_final(const float* __restrict__ h, const float* __restrict__ W,
                        const float* __restrict__ b, float* __restrict__ out) {
    int warp = (blockIdx.x * blockDim.x + threadIdx.x) >> 5;
    int lane = threadIdx.x & 31;
    if (warp >= N_NODES) return;
    float p0 = 0.f, p1 = 0.f;
#pragma unroll
    for (int j = 0; j < 4; j++) {
        int k = lane + 32 * j;
        float hv = h[(size_t)warp * FDIM + k];
        p0 += hv * W[k * 2];
        p1 += hv * W[k * 2 + 1];
    }
    for (int o = 16; o; o >>= 1) {
        p0 += __shfl_down_sync(0xFFFFFFFFu, p0, o);
        p1 += __shfl_down_sync(0xFFFFFFFFu, p1, o);
    }
    if (lane == 0) {
        float l0 = p0 + b[0], l1 = p1 + b[1];
        float m = fmaxf(l0, l1);
        float ls = m + logf(expf(l0 - m) + expf(l1 - m));
        out[warp * 2]     = l0 - ls;
        out[warp * 2 + 1] = l1 - ls;
    }
}

// ================= host launcher =================
#define GSYM(var, sym) float* var; { void* _p = 0; cudaGetSymbolAddress(&_p, sym); var = (float*)_p; }

extern "C" void kernel_launch(void* const* d_in, const int* in_sizes, int n_in,
                              void* d_out, int out_size) {
    const float* x    = (const float*)d_in[0];
    const float* xcov = (const float*)d_in[1];
    const int*   er   = (const int*)d_in[2];
    const int*   ec   = (const int*)d_in[3];
    const float* adjv = (const float*)d_in[4];
    const float* nv   = (const float*)d_in[5];
    const float* gam  = (const float*)d_in[6];
    const float* bet  = (const float*)d_in[7];
    const float* c0W1 = (const float*)d_in[8];
    const float* c0b1 = (const float*)d_in[9];
    const float* c0W2 = (const float*)d_in[10];
    const float* c0b2 = (const float*)d_in[11];
    const float* c1W1 = (const float*)d_in[12];
    const float* c1b1 = (const float*)d_in[13];
    const float* c1W2 = (const float*)d_in[14];
    const float* c1b2 = (const float*)d_in[15];
    // c2_* (d_in[16..19]) are dead code in the reference
    const float* mW1 = (const float*)d_in[20];
    const float* mb1 = (const float*)d_in[21];
    const float* a1  = (const float*)d_in[22];
    const float* mW2 = (const float*)d_in[23];
    const float* mb2 = (const float*)d_in[24];
    const float* a2  = (const float*)d_in[25];
    const float* mW3 = (const float*)d_in[26];
    const float* mb3 = (const float*)d_in[27];

    float* outLog = (float*)d_out;
    float* outAdj = (float*)d_out + (size_t)N_NODES * 2;

    GSYM(xp0, g_xp0)   GSYM(xp1, g_xp1)
    GSYM(hA,  g_hA)    GSYM(hB1, g_hB1)   GSYM(hB2, g_hB2)
    GSYM(S0,  g_S0)    GSYM(corr0, g_corr0)
    GSYM(cs0, g_cs0)   GSYM(cs1, g_cs1)
    GSYM(xc1, g_xc1)   GSYM(corr1, g_corr1) GSYM(T0, g_T0) GSYM(G0, g_G0)
    GSYM(S1,  g_S1)    GSYM(xc2, g_xc2)   GSYM(corr2, g_corr2)
    GSYM(T1,  g_T1)    GSYM(G1,  g_G1)    GSYM(P1,  g_P1)
    GSYM(pa1, g_pa1)   GSYM(pa2, g_pa2)   GSYM(pc1, g_pc1)
    GSYM(csA, g_csA)   GSYM(cssA, g_cssA)
    GSYM(csB, g_csB)   GSYM(qB, g_qB)
    GSYM(csC, g_csC)   GSYM(qC, g_qC)
    GSYM(pb1, g_pb1)   GSYM(pb2, g_pb2)
    GSYM(csX, g_csX)   GSYM(cssX, g_cssX)
    GSYM(tnp, g_tnpart) GSYM(tnp2, g_tnpart2)
    GSYM(mBbuf, g_mB)

    const int MASKW_SMEM = 67072;
    const int NN3_SMEM = 55296;
    cudaFuncSetAttribute(k_mask_w, cudaFuncAttributeMaxDynamicSharedMemorySize,
                         MASKW_SMEM);
    cudaFuncSetAttribute(k_nn_mma3, cudaFuncAttributeMaxDynamicSharedMemorySize,
                         NN3_SMEM);

    cudaStream_t s2, s3;
    cudaStreamCreateWithFlags(&s2, cudaStreamNonBlocking);
    cudaStreamCreateWithFlags(&s3, cudaStreamNonBlocking);
    cudaEvent_t evFork, evJoin, evCorr0, evS0, evCs0, evG0, evL1;
    cudaEventCreateWithFlags(&evFork, cudaEventDisableTiming);
    cudaEventCreateWithFlags(&evJoin, cudaEventDisableTiming);
    cudaEventCreateWithFlags(&evCorr0, cudaEventDisableTiming);
    cudaEventCreateWithFlags(&evS0, cudaEventDisableTiming);
    cudaEventCreateWithFlags(&evCs0, cudaEventDisableTiming);
    cudaEventCreateWithFlags(&evG0, cudaEventDisableTiming);
    cudaEventCreateWithFlags(&evL1, cudaEventDisableTiming);

    k_zero<<<(N_NODES + 1023) / 1024, 1024>>>();
    cudaEventRecord(evFork, 0);
    cudaStreamWaitEvent(s2, evFork, 0);
    cudaStreamWaitEvent(s3, evFork, 0);

    // ============ chain B (s2): stats -> CSR -> prop(BN-fused) -> MLP -> outLog ===
    k_psum<<<250, 128, 0, s2>>>(x, N_NODES, FDIM, 32, pb1, pb2);
    k_preduce<<<1, 128, 0, s2>>>(pb1, pb2, 250, FDIM, N_NODES, csX, cssX);
    k_count<<<EDGES / 256, 256, 0, s2>>>(er);
    k_scan<<<1, 1024, 0, s2>>>();
    k_scatter<<<EDGES / 256, 256, 0, s2>>>(er, ec, nv);

    k_prop_bn<<<N_NODES / 2, 256, 0, s2>>>(x, csX, cssX, gam, bet, xp0);
    {
        const float* cur = xp0;
        float* bufs[2] = {xp1, xp0};
        for (int it = 0; it < 9; it++) {
            float* o = bufs[it & 1];
            k_prop<<<N_NODES / 2, 256, 0, s2>>>(cur, o);
            cur = o;
        }
        // ends in xp1
    }
    k_nn_mma3<<<dim3(63, 2), 256, NN3_SMEM, s2>>>(N_NODES, FDIM, xp1, mW1, mb1, hB1, 2, a1);
    k_nn_mma3<<<dim3(63, 2), 256, NN3_SMEM, s2>>>(N_NODES, FDIM, hB1, mW2, mb2, hB2, 2, a2);
    k_final<<<(N_NODES * 32 + 255) / 256, 256, 0, s2>>>(hB2, mW3, mb3, outLog);

    // ============ chain C part 1 (s3): corr0 ============
    k_psum<<<250, 128, 0, s3>>>(xcov, N_NODES, FDIM, 32, pa1, pa2);
    k_preduce<<<1, 128, 0, s3>>>(pa1, pa2, 250, FDIM, N_NODES, csA, cssA);
    k_corr<<<N_NODES, 128, 0, s3>>>(xcov, N_NODES, csA, cssA, corr0, 0, 0, 0);
    cudaEventRecord(evCorr0, s3);

    // ============ chain A (stream 0): cluster MLP -> softmax ============
    k_nn_mma3<<<dim3(63, 2), 256, NN3_SMEM>>>(N_NODES, FDIM, xcov, c0W1, c0b1, hA, 1, 0);
    k_nn_mma3<<<dim3(63, 7), 256, NN3_SMEM>>>(N_NODES, C0, hA, c0W2, c0b2, S0, 0, 0);
    k_softmax400<<<N_NODES, 128>>>(S0);
    cudaEventRecord(evS0, 0);

    // ============ chain C part 2 (s3): S0 colsum ============
    cudaStreamWaitEvent(s3, evS0, 0);
    k_psum<<<250, 128, 0, s3>>>(S0, N_NODES, C0, 32, pc1, 0);
    k_preduce<<<4, 128, 0, s3>>>(pc1, 0, 250, C0, N_NODES, cs0, 0);
    cudaEventRecord(evCs0, s3);

    // ============ chain A continues (stream 0) ============
    cudaStreamWaitEvent(0, evCorr0, 0);
    k_tn_mma<<<dim3(7, ZSPLIT), 256>>>(S0, xcov, corr0, tnp, tnp2);
    cudaStreamWaitEvent(0, evCs0, 0);
    k_tn_red2<<<(C0 * FDIM + 255) / 256, 256>>>(tnp, tnp2, ZSPLIT, C0, FDIM, cs0,
                                                xc1, T0, csB, qB);
    k_corr<<<C0, 128>>>(xc1, C0, csB, qB, corr1, T0, G0, 1);
    cudaEventRecord(evG0, 0);

    // mask MMA writer starts immediately (depends only on S0 + G0)
    k_mask_w<<<EDGES / 128, 256, MASKW_SMEM>>>(S0, G0, er, ec, mBbuf);

    // ============ chain C part 3 (s3): level-1 + P1, overlapped with mask MMA ====
    cudaStreamWaitEvent(s3, evG0, 0);
    k_nn_mma3<<<dim3(4, 2), 256, NN3_SMEM, s3>>>(C0, FDIM, xc1, c1W1, c1b1, hA, 1, 0);
    k_nn_mma3<<<dim3(4, 1), 256, NN3_SMEM, s3>>>(C0, C1, hA, c1W2, c1b2, S1, 0, 0);
    k_softmax20<<<50, 256, 0, s3>>>(S1, cs1);
    k_tn16<<<C1, 128, 0, s3>>>(S1, xc1, corr1, cs1, xc2, T1, csC, qC);
    k_corr<<<C1, 128, 0, s3>>>(xc2, C1, csC, qC, corr2, T1, G1, 1);
    k_gemm_nn<<<dim3(125, 1), 256, 0, s3>>>(N_NODES, C1, C0, S0, S1, 0, P1, 0, 0);
    cudaEventRecord(evL1, s3);

    // ============ carry (stream 0) after mask MMA and level-1 ============
    cudaStreamWaitEvent(0, evL1, 0);
    k_carry_g<<<EDGES / 256, 256>>>(P1, G1, er, ec, adjv, mBbuf, outAdj);

    // ============ join ============
    cudaEventRecord(evJoin, s2);
    cudaStreamWaitEvent(0, evJoin, 0);

    cudaEventDestroy(evFork);
    cudaEventDestroy(evJoin);
    cudaEventDestroy(evCorr0);
    cudaEventDestroy(evS0);
    cudaEventDestroy(evCs0);
    cudaEventDestroy(evG0);
    cudaEventDestroy(evL1);
    cudaStreamDestroy(s2);
    cudaStreamDestroy(s3);

    (void)in_sizes; (void)n_in; (void)out_size;
}

// round 16
// speedup vs baseline: 1.0499x; 1.0499x over previous
#include <cuda_runtime.h>
#include <math.h>

#define N_NODES 8000
#define FDIM    128
#define EDGES   256000
#define C0      400
#define C1      20
#define ZSPLIT  25

// ---------------- static device scratch (no runtime allocation) ----------------
__device__ float g_xp0[N_NODES*FDIM];
__device__ float g_xp1[N_NODES*FDIM];
__device__ float g_hA [N_NODES*FDIM];
__device__ float g_hB1[N_NODES*FDIM];
__device__ float g_hB2[N_NODES*FDIM];
__device__ float g_S0 [N_NODES*C0];
__device__ float g_corr0[N_NODES*FDIM];
__device__ float g_cs0[C0];
__device__ float g_cs1[C1];
__device__ float g_xc1  [C0*FDIM];
__device__ float g_corr1[C0*FDIM];
__device__ float g_T0   [C0*FDIM];
__device__ float g_G0   [C0*FDIM];
__device__ float g_S1   [C0*C1];
__device__ float g_xc2  [C1*FDIM];
__device__ float g_corr2[C1*FDIM];
__device__ float g_T1   [C1*FDIM];
__device__ float g_G1   [C1*FDIM];
__device__ float g_P1   [N_NODES*C1];
__device__ float g_pa1[250*C0];
__device__ float g_pa2[250*C0];
__device__ float g_pc1[250*C0];
__device__ float g_csA[FDIM];
__device__ float g_cssA[FDIM];
__device__ float g_csB[FDIM];
__device__ float g_qB [FDIM];
__device__ float g_csC[FDIM];
__device__ float g_qC [FDIM];
__device__ float g_pb1[250*FDIM];
__device__ float g_pb2[250*FDIM];
__device__ float g_csX[FDIM];
__device__ float g_cssX[FDIM];
__device__ float g_tnpart [ZSPLIT*C0*FDIM];
__device__ float g_tnpart2[ZSPLIT*C0*FDIM];
__device__ int   g_cnt[N_NODES];
__device__ int   g_off[N_NODES+1];
__device__ int   g_cur[N_NODES];
__device__ float2 g_ePk[EDGES];   // packed (col-as-float-bits, weight)

// ---------------- zero all atomic-accumulated buffers + cnt (one launch) --------
__global__ void k_zero() {
    int i = blockIdx.x * blockDim.x + threadIdx.x;
    if (i < N_NODES) g_cnt[i] = 0;
    if (i < FDIM) { g_csB[i] = 0.f; g_qB[i] = 0.f; g_csC[i] = 0.f; g_qC[i] = 0.f; }
    if (i < C1) g_cs1[i] = 0.f;
}

// ---------------- two-stage deterministic column stats ----------------
__global__ void k_psum(const float* __restrict__ A, int n, int c, int rowsPer,
                       float* __restrict__ ps, float* __restrict__ pq) {
    int b = blockIdx.x;
    int r0 = b * rowsPer, r1 = min(n, r0 + rowsPer);
    for (int col = threadIdx.x; col < c; col += blockDim.x) {
        float s = 0.f, q = 0.f;
        for (int r = r0; r < r1; r++) {
            float v = A[(size_t)r * c + col];
            s += v; q += v * v;
        }
        ps[(size_t)b * c + col] = s;
        if (pq) pq[(size_t)b * c + col] = q;
    }
}

__global__ void k_preduce(const float* __restrict__ ps, const float* __restrict__ pq,
                          int nb, int c, int n,
                          float* __restrict__ outS, float* __restrict__ outCss) {
    int col = blockIdx.x * blockDim.x + threadIdx.x;
    if (col >= c) return;
    float s = 0.f, q = 0.f;
    for (int b = 0; b < nb; b++) {
        s += ps[(size_t)b * c + col];
        if (pq) q += pq[(size_t)b * c + col];
    }
    outS[col] = s;
    if (outCss) outCss[col] = q - s * s / (float)n;
}

// ---------------- node correlation (+ optional fused gains) ----------------
__global__ void k_corr(const float* __restrict__ z, int n,
                       const float* __restrict__ cs, const float* __restrict__ cssOrQ,
                       float* __restrict__ out,
                       const float* __restrict__ T, float* __restrict__ G, int rawq) {
    int r = blockIdx.x, f = threadIdx.x;
    float s = cs[f];
    float mean = s / (float)n;
    float css = rawq ? (cssOrQ[f] - s * s / (float)n) : cssOrQ[f];
    float inv = 1.f / (sqrtf(css) + 1e-12f);
    float v = (z[(size_t)r * FDIM + f] - mean) * inv;
    __shared__ float red[128];
    red[f] = v; __syncthreads();
    for (int st = 64; st > 0; st >>= 1) {
        if (f < st) red[f] += red[f + st];
        __syncthreads();
    }
    size_t idx = (size_t)r * FDIM + f;
    float cv = v * red[0];
    out[idx] = cv;
    if (T) {
        float x = 1.f / (1.f + expf(T[idx] - cv));
        G[idx] = x * x;
    }
}

// ---------------- softmax for S0 rows (W=400), register-resident ----------------
__global__ void k_softmax400(float* __restrict__ X) {
    int r = blockIdx.x;
    float* row = X + (size_t)r * C0;
    int t = threadIdx.x;
    int cnt = (t < C0 - 3 * 128) ? 4 : 3;
    float v[4];
    float m = -3.4e38f;
#pragma unroll
    for (int j = 0; j < 4; j++) {
        if (j < cnt) { v[j] = row[t + 128 * j]; m = fmaxf(m, v[j]); }
    }
    __shared__ float red[128];
    red[t] = m; __syncthreads();
    for (int s = 64; s > 0; s >>= 1) {
        if (t < s) red[t] = fmaxf(red[t], red[t + s]);
        __syncthreads();
    }
    m = red[0]; __syncthreads();
    float sum = 0.f;
#pragma unroll
    for (int j = 0; j < 4; j++) {
        if (j < cnt) { v[j] = expf(v[j] - m); sum += v[j]; }
    }
    red[t] = sum; __syncthreads();
    for (int s = 64; s > 0; s >>= 1) {
        if (t < s) red[t] += red[t + s];
        __syncthreads();
    }
    float inv = 1.f / red[0];
#pragma unroll
    for (int j = 0; j < 4; j++) {
        if (j < cnt) row[t + 128 * j] = v[j] * inv;
    }
}

// ---------------- softmax for S1 rows (W=20), warp/row + fused colsum ----------
__global__ void k_softmax20(float* __restrict__ X, float* __restrict__ cs) {
    int warp = (blockIdx.x * blockDim.x + threadIdx.x) >> 5;
    int lane = threadIdx.x & 31;
    if (warp >= C0) return;
    float* row = X + (size_t)warp * C1;
    float v = (lane < C1) ? row[lane] : -3.4e38f;
    float m = v;
#pragma unroll
    for (int o = 16; o; o >>= 1) m = fmaxf(m, __shfl_xor_sync(0xFFFFFFFFu, m, o));
    float e = (lane < C1) ? expf(v - m) : 0.f;
    float s = e;
#pragma unroll
    for (int o = 16; o; o >>= 1) s += __shfl_xor_sync(0xFFFFFFFFu, s, o);
    if (lane < C1) {
        float val = e / s;
        row[lane] = val;
        atomicAdd(&cs[lane], val);
    }
}

// ---------------- tf32 helper ----------------
__device__ __forceinline__ unsigned tf32r(float x) {
    unsigned u;
    asm("cvt.rna.tf32.f32 %0, %1;" : "=r"(u) : "f"(x));
    return u;
}

#define MMA_TF32(ACC, A0, A1, A2, A3, B0, B1)                                  \
    asm volatile(                                                              \
        "mma.sync.aligned.m16n8k8.row.col.f32.tf32.tf32.f32 "                  \
        "{%0,%1,%2,%3}, {%4,%5,%6,%7}, {%8,%9}, {%0,%1,%2,%3};"                \
        : "+f"(ACC[0]), "+f"(ACC[1]), "+f"(ACC[2]), "+f"(ACC[3])               \
        : "r"(A0), "r"(A1), "r"(A2), "r"(A3), "r"(B0), "r"(B1))

// ---------------- split-3 tf32 NN GEMM (fp32-accurate): C = act(A@B + bias) -----
__global__ void __launch_bounds__(256)
k_nn_mma3(int M, int N,
          const float* __restrict__ A, const float* __restrict__ B,
          const float* __restrict__ bias, float* __restrict__ C,
          int act, const float* __restrict__ aux) {
    extern __shared__ __align__(16) char sm3[];
    unsigned (*Ah)[36] = (unsigned(*)[36])(sm3);
    unsigned (*Al)[36] = (unsigned(*)[36])(sm3 + 18432);
    unsigned (*Bh)[72] = (unsigned(*)[72])(sm3 + 36864);
    unsigned (*Bl)[72] = (unsigned(*)[72])(sm3 + 46080);
    int t = threadIdx.x, lane = t & 31, w = t >> 5;
    int m0 = blockIdx.x * 128, n0 = blockIdx.y * 64;
    float acc[8][4];
#pragma unroll
    for (int nt = 0; nt < 8; nt++)
#pragma unroll
        for (int i = 0; i < 4; i++) acc[nt][i] = 0.f;

    for (int k0 = 0; k0 < 128; k0 += 32) {
        for (int idx = t; idx < 128 * 32; idx += 256) {
            int r = idx >> 5, kk = idx & 31;
            int row = m0 + r;
            float v = (row < M) ? A[(size_t)row * 128 + k0 + kk] : 0.f;
            unsigned h = tf32r(v);
            Ah[r][kk] = h;
            Al[r][kk] = tf32r(v - __uint_as_float(h));
        }
        for (int idx = t; idx < 32 * 64; idx += 256) {
            int kk = idx >> 6, n = idx & 63;
            int col = n0 + n;
            float v = (col < N) ? B[(size_t)(k0 + kk) * N + col] : 0.f;
            unsigned h = tf32r(v);
            Bh[kk][n] = h;
            Bl[kk][n] = tf32r(v - __uint_as_float(h));
        }
        __syncthreads();
#pragma unroll
        for (int ks = 0; ks < 4; ks++) {
            int kb = ks * 8;
            int ar = w * 16 + (lane >> 2);
            int ak = kb + (lane & 3);
            unsigned ah0 = Ah[ar][ak],     ah1 = Ah[ar + 8][ak];
            unsigned ah2 = Ah[ar][ak + 4], ah3 = Ah[ar + 8][ak + 4];
            unsigned al0 = Al[ar][ak],     al1 = Al[ar + 8][ak];
            unsigned al2 = Al[ar][ak + 4], al3 = Al[ar + 8][ak + 4];
#pragma unroll
            for (int nt = 0; nt < 8; nt++) {
                int bn = nt * 8 + (lane >> 2);
                unsigned bh0 = Bh[kb + (lane & 3)][bn];
                unsigned bh1 = Bh[kb + (lane & 3) + 4][bn];
                unsigned bl0 = Bl[kb + (lane & 3)][bn];
                unsigned bl1 = Bl[kb + (lane & 3) + 4][bn];
                MMA_TF32(acc[nt], ah0, ah1, ah2, ah3, bh0, bh1);
                MMA_TF32(acc[nt], ah0, ah1, ah2, ah3, bl0, bl1);
                MMA_TF32(acc[nt], al0, al1, al2, al3, bh0, bh1);
            }
        }
        __syncthreads();
    }
    float slope = (act == 2) ? aux[0] : 0.f;
    int rbase = m0 + w * 16 + (lane >> 2);
#pragma unroll
    for (int nt = 0; nt < 8; nt++) {
        int cb = n0 + nt * 8 + 2 * (lane & 3);
#pragma unroll
        for (int q = 0; q < 4; q++) {
            int r = rbase + ((q >= 2) ? 8 : 0);
            int c = cb + (q & 1);
            if (r < M && c < N) {
                float v = acc[nt][q];
                if (bias) v += bias[c];
                if (act == 1) v = fmaxf(v, 0.f);
                else if (act == 2) v = (v >= 0.f) ? v : slope * v;
                C[(size_t)r * N + c] = v;
            }
        }
    }
}

// ---------------- generic tiled SIMT GEMM (small uses) ----------------
__global__ void k_gemm_nn(int M, int N, int K,
                          const float* __restrict__ A, const float* __restrict__ B,
                          const float* __restrict__ bias, float* __restrict__ C,
                          int act, const float* __restrict__ aux) {
    __shared__ __align__(16) float As[16][68];
    __shared__ __align__(16) float Bs[16][64];
    int t = threadIdx.x;
    int m0 = blockIdx.x * 64, n0 = blockIdx.y * 64;
    int tx = t & 15, ty = t >> 4;
    float acc[4][4];
#pragma unroll
    for (int i = 0; i < 4; i++)
#pragma unroll
        for (int j = 0; j < 4; j++) acc[i][j] = 0.f;
    for (int k0 = 0; k0 < K; k0 += 16) {
        __syncthreads();
        for (int idx = t; idx < 1024; idx += 256) {
            int kk = idx & 15, r = idx >> 4;
            int row = m0 + r;
            As[kk][r] = (row < M) ? A[(size_t)row * K + k0 + kk] : 0.f;
        }
        for (int idx = t; idx < 1024; idx += 256) {
            int kk = idx >> 6, c = idx & 63;
            int col = n0 + c;
            Bs[kk][c] = (col < N) ? B[(size_t)(k0 + kk) * N + col] : 0.f;
        }
        __syncthreads();
#pragma unroll
        for (int kk = 0; kk < 16; kk++) {
            float4 av = *(const float4*)&As[kk][ty * 4];
            float4 bv = *(const float4*)&Bs[kk][tx * 4];
            float a4[4] = {av.x, av.y, av.z, av.w};
            float b4[4] = {bv.x, bv.y, bv.z, bv.w};
#pragma unroll
            for (int i = 0; i < 4; i++)
#pragma unroll
                for (int j = 0; j < 4; j++) acc[i][j] += a4[i] * b4[j];
        }
    }
    float slope = (act == 2) ? aux[0] : 0.f;
#pragma unroll
    for (int i = 0; i < 4; i++) {
        int row = m0 + ty * 4 + i;
        if (row >= M) continue;
#pragma unroll
        for (int j = 0; j < 4; j++) {
            int col = n0 + tx * 4 + j;
            if (col >= N) continue;
            float v = acc[i][j];
            if (bias) v += bias[col];
            if (act == 1) v = fmaxf(v, 0.f);
            else if (act == 2) v = (v >= 0.f) ? v : slope * v;
            C[(size_t)row * N + col] = v;
        }
    }
}

// ---------------- tf32 MMA TN GEMM (split-m) ----------------
__global__ void __launch_bounds__(256)
k_tn_mma(const float* __restrict__ A,
         const float* __restrict__ B1, const float* __restrict__ B2,
         float* __restrict__ part1, float* __restrict__ part2) {
    __shared__ unsigned As[64][33];
    __shared__ unsigned Bs1[32][136];
    __shared__ unsigned Bs2[32][136];
    int t = threadIdx.x, lane = t & 31, w = t >> 5;
    int wr = w & 3, wc = w >> 2;
    int k10 = blockIdx.x * 64;
    int mBase = blockIdx.y * 320;
    float acc1[8][4], acc2[8][4];
#pragma unroll
    for (int nt = 0; nt < 8; nt++)
#pragma unroll
        for (int i = 0; i < 4; i++) { acc1[nt][i] = 0.f; acc2[nt][i] = 0.f; }

    for (int mc = 0; mc < 320; mc += 32) {
        for (int idx = t; idx < 2048; idx += 256) {
            int m = idx >> 6, kl = idx & 63;
            int k1 = k10 + kl;
            float v = (k1 < C0) ? A[(size_t)(mBase + mc + m) * C0 + k1] : 0.f;
            As[kl][m] = tf32r(v);
        }
        for (int idx = t; idx < 4096; idx += 256) {
            int m = idx >> 7, n = idx & 127;
            size_t g = (size_t)(mBase + mc + m) * FDIM + n;
            Bs1[m][n] = tf32r(B1[g]);
            Bs2[m][n] = tf32r(B2[g]);
        }
        __syncthreads();
#pragma unroll
        for (int ks = 0; ks < 4; ks++) {
            int ar = wr * 16 + (lane >> 2);
            int ak = ks * 8 + (lane & 3);
            unsigned a0 = As[ar][ak];
            unsigned a1 = As[ar + 8][ak];
            unsigned a2 = As[ar][ak + 4];
            unsigned a3 = As[ar + 8][ak + 4];
#pragma unroll
            for (int nt = 0; nt < 8; nt++) {
                int bn = wc * 64 + nt * 8 + (lane >> 2);
                unsigned b0 = Bs1[ks * 8 + (lane & 3)][bn];
                unsigned b1 = Bs1[ks * 8 + (lane & 3) + 4][bn];
                MMA_TF32(acc1[nt], a0, a1, a2, a3, b0, b1);
                unsigned c0 = Bs2[ks * 8 + (lane & 3)][bn];
                unsigned c1 = Bs2[ks * 8 + (lane & 3) + 4][bn];
                MMA_TF32(acc2[nt], a0, a1, a2, a3, c0, c1);
            }
        }
        __syncthreads();
    }
    int z = blockIdx.y;
    int k1r = k10 + wr * 16 + (lane >> 2);
    int cb = 2 * (lane & 3);
#pragma unroll
    for (int nt = 0; nt < 8; nt++) {
        int n = wc * 64 + nt * 8 + cb;
        if (k1r < C0) {
            size_t b = ((size_t)z * C0 + k1r) * FDIM + n;
            part1[b] = acc1[nt][0]; part1[b + 1] = acc1[nt][1];
            part2[b] = acc2[nt][0]; part2[b + 1] = acc2[nt][1];
        }
        if (k1r + 8 < C0) {
            size_t b = ((size_t)z * C0 + k1r + 8) * FDIM + n;
            part1[b] = acc1[nt][2]; part1[b + 1] = acc1[nt][3];
            part2[b] = acc2[nt][2]; part2[b + 1] = acc2[nt][3];
        }
    }
}

// dual reduce + fused atomic column-stats of out1 (if csS!=0)
__global__ void k_tn_red2(const float* __restrict__ part1, const float* __restrict__ part2,
                          int S, int K1, int N,
                          const float* __restrict__ divrow,
                          float* __restrict__ out1, float* __restrict__ out2,
                          float* __restrict__ csS, float* __restrict__ qS) {
    int i = blockIdx.x * blockDim.x + threadIdx.x;
    if (i >= K1 * N) return;
    float s1 = 0.f, s2 = 0.f;
    for (int b = 0; b < S; b++) {
        s1 += part1[(size_t)b * K1 * N + i];
        s2 += part2[(size_t)b * K1 * N + i];
    }
    if (divrow) s1 /= (divrow[i / N] + 1e-12f);
    out1[i] = s1;
    out2[i] = s2;
    if (csS) {
        int f = i % N;
        atomicAdd(&csS[f], s1);
        atomicAdd(&qS[f], s1 * s1);
    }
}

// ---------------- fused level-1 TN: xc2 = S1^T@xc1/cs1, T1 = S1^T@corr1 ----------
__global__ void k_tn16(const float* __restrict__ S1,
                       const float* __restrict__ B1, const float* __restrict__ B2,
                       const float* __restrict__ cs1,
                       float* __restrict__ out1, float* __restrict__ out2,
                       float* __restrict__ csS, float* __restrict__ qS) {
    int k1 = blockIdx.x, f = threadIdx.x;
    float a1 = 0.f, a2 = 0.f;
    for (int m = 0; m < C0; m++) {
        float s = S1[m * C1 + k1];
        a1 += s * B1[(size_t)m * FDIM + f];
        a2 += s * B2[(size_t)m * FDIM + f];
    }
    float o1 = a1 / (cs1[k1] + 1e-12f);
    out1[(size_t)k1 * FDIM + f] = o1;
    out2[(size_t)k1 * FDIM + f] = a2;
    atomicAdd(&csS[f], o1);
    atomicAdd(&qS[f], o1 * o1);
}

// ---------------- FUSED: mask(K=400 MMA) + mask(K=20) + serial carry ----------------
__global__ void __launch_bounds__(256, 2)
k_fused_mask(const float* __restrict__ s0p, const float* __restrict__ g0sq,
             const float* __restrict__ p1, const float* __restrict__ g1sq,
             const int* __restrict__ er, const int* __restrict__ ec,
             const float* __restrict__ adjv, float* __restrict__ outAdj) {
    extern __shared__ __align__(16) char sm[];
    unsigned (*Us)[36]  = (unsigned(*)[36])(sm);
    unsigned (*Gs)[136] = (unsigned(*)[136])(sm + 18432);
    float (*Ms)[129]    = (float(*)[129])(sm);
    float (*G1s)[128]   = (float(*)[128])(sm + 66048);
    int* rr             = (int*)(sm + 76288);
    int* cc             = (int*)(sm + 76800);

    int t = threadIdx.x, lane = t & 31, w = t >> 5;
    int e0 = blockIdx.x * 128;
    if (t < 128) { rr[t] = er[e0 + t]; cc[t] = ec[e0 + t]; }
    for (int idx = t; idx < C1 * FDIM; idx += 256)
        G1s[idx >> 7][idx & 127] = g1sq[idx];
    float acc[16][4];
#pragma unroll
    for (int nt = 0; nt < 16; nt++)
#pragma unroll
        for (int i = 0; i < 4; i++) acc[nt][i] = 0.f;
    __syncthreads();

    for (int k0 = 0; k0 < C0; k0 += 32) {
        for (int idx = t; idx < 32 * 128; idx += 256) {
            int kk = idx >> 7, f = idx & 127;
            float v = (k0 + kk < C0) ? g0sq[(size_t)(k0 + kk) * FDIM + f] : 0.f;
            Gs[kk][f] = tf32r(v);
        }
        for (int idx = t; idx < 128 * 32; idx += 256) {
            int kk = idx & 31, e = idx >> 5;
            float v = 0.f;
            if (k0 + kk < C0)
                v = s0p[(size_t)rr[e] * C0 + k0 + kk] * s0p[(size_t)cc[e] * C0 + k0 + kk];
            Us[e][kk] = tf32r(v);
        }
        __syncthreads();
#pragma unroll
        for (int ks = 0; ks < 4; ks++) {
            int kb = ks * 8;
            int ar = w * 16 + (lane >> 2);
            int ak = kb + (lane & 3);
            unsigned a0 = Us[ar][ak];
            unsigned a1 = Us[ar + 8][ak];
            unsigned a2 = Us[ar][ak + 4];
            unsigned a3 = Us[ar + 8][ak + 4];
#pragma unroll
            for (int nt = 0; nt < 16; nt++) {
                int bn = nt * 8 + (lane >> 2);
                unsigned b0 = Gs[kb + (lane & 3)][bn];
                unsigned b1 = Gs[kb + (lane & 3) + 4][bn];
                MMA_TF32(acc[nt], a0, a1, a2, a3, b0, b1);
            }
        }
        __syncthreads();
    }
    {
        int r = w * 16 + (lane >> 2);
        int cb = 2 * (lane & 3);
#pragma unroll
        for (int nt = 0; nt < 16; nt++) {
            int c = nt * 8 + cb;
            Ms[c][r]         = acc[nt][0];
            Ms[c + 1][r]     = acc[nt][1];
            Ms[c][r + 8]     = acc[nt][2];
            Ms[c + 1][r + 8] = acc[nt][3];
        }
    }
    __syncthreads();
    if (t < 128) {
        int e = t;
        float u20[C1];
        const float* pr = p1 + (size_t)rr[e] * C1;
        const float* pc = p1 + (size_t)cc[e] * C1;
#pragma unroll
        for (int k = 0; k < C1; k++) u20[k] = pr[k] * pc[k];
        float a = adjv[e0 + e];
        for (int f = 0; f < FDIM; f++) {
            float mA = 0.f;
#pragma unroll
            for (int k = 0; k < C1; k++) mA += u20[k] * G1s[k][f];
            float mB = Ms[f][e];
            float tq = a * mA;
            outAdj[(size_t)f * EDGES + e0 + e] = tq + tq * mB;
            a = tq * mB;
        }
    }
}

// ---------------- CSR build ----------------
__global__ void k_count(const int* __restrict__ er) {
    int e = blockIdx.x * blockDim.x + threadIdx.x;
    if (e < EDGES) atomicAdd(&g_cnt[er[e]], 1);
}

__global__ void k_scan() {
    __shared__ int part[1024];
    const int n = N_NODES;
    const int per = (n + 1023) / 1024;
    int t = threadIdx.x;
    int s = 0;
    int lo = t * per, hi = min(n, (t + 1) * per);
    for (int i = lo; i < hi; i++) s += g_cnt[i];
    part[t] = s; __syncthreads();
    for (int off = 1; off < 1024; off <<= 1) {
        int v = (t >= off) ? part[t - off] : 0;
        __syncthreads();
        part[t] += v;
        __syncthreads();
    }
    int base = (t == 0) ? 0 : part[t - 1];
    for (int i = lo; i < hi; i++) {
        g_off[i] = base; g_cur[i] = base; base += g_cnt[i];
    }
    if (t == 1023) g_off[n] = base;
}

__global__ void k_scatter(const int* __restrict__ er, const int* __restrict__ ec,
                          const float* __restrict__ nv) {
    int e = blockIdx.x * blockDim.x + threadIdx.x;
    if (e < EDGES) {
        int pos = atomicAdd(&g_cur[er[e]], 1);
        g_ePk[pos] = make_float2(__int_as_float(ec[e]), nv[e]);
    }
}

// ---------------- propagation step with fused BN (packed edges) ----------------
__global__ void k_prop_bn(const float* __restrict__ x,
                          const float* __restrict__ cs, const float* __restrict__ css,
                          const float* __restrict__ gam, const float* __restrict__ bet,
                          float* __restrict__ xout) {
    int r = blockIdx.x * 2 + (threadIdx.x >> 7);
    int f = threadIdx.x & 127;
    float mu   = cs[f]  * (1.f / N_NODES);
    float var  = css[f] * (1.f / N_NODES);
    float rstd = rsqrtf(var + 1e-5f);
    float scale = gam[f] * rstd;
    float shift = bet[f] - mu * scale;
    float acc = 0.f;
    int s = g_off[r], e = g_off[r + 1];
    for (int i = s; i < e; i++) {
        float2 pk = g_ePk[i];
        int c = __float_as_int(pk.x);
        acc += pk.y * (x[(size_t)c * FDIM + f] * scale + shift);
    }
    xout[(size_t)r * FDIM + f] = acc;
}

// ---------------- plain propagation step (packed edges, 2 nodes/block) ----------
__global__ void k_prop(const float* __restrict__ xin, float* __restrict__ xout) {
    int r = blockIdx.x * 2 + (threadIdx.x >> 7);
    int f = threadIdx.x & 127;
    float acc = 0.f;
    int s = g_off[r], e = g_off[r + 1];
    for (int i = s; i < e; i++) {
        float2 pk = g_ePk[i];
        int c = __float_as_int(pk.x);
        acc += pk.y * xin[(size_t)c * FDIM + f];
    }
    xout[(size_t)r * FDIM + f] = acc;
}

// ---------------- final logits + log_softmax ----------------
__global__ void k_final(const float* __restrict__ h, const float* __restrict__ W,
                        const float* __restrict__ b, float* __restrict__ out) {
    int warp = (blockIdx.x * blockDim.x + threadIdx.x) >> 5;
    int lane = threadIdx.x & 31;
    if (warp >= N_NODES) return;
    float p0 = 0.f, p1 = 0.f;
#pragma unroll
    for (int j = 0; j < 4; j++) {
        int k = lane + 32 * j;
        float hv = h[(size_t)warp * FDIM + k];
        p0 += hv * W[k * 2];
        p1 += hv * W[k * 2 + 1];
    }
    for (int o = 16; o; o >>= 1) {
        p0 += __shfl_down_sync(0xFFFFFFFFu, p0, o);
        p1 += __shfl_down_sync(0xFFFFFFFFu, p1, o);
    }
    if (lane == 0) {
        float l0 = p0 + b[0], l1 = p1 + b[1];
        float m = fmaxf(l0, l1);
        float ls = m + logf(expf(l0 - m) + expf(l1 - m));
        out[warp * 2]     = l0 - ls;
        out[warp * 2 + 1] = l1 - ls;
    }
}

// ================= host launcher =================
#define GSYM(var, sym) float* var; { void* _p = 0; cudaGetSymbolAddress(&_p, sym); var = (float*)_p; }

extern "C" void kernel_launch(void* const* d_in, const int* in_sizes, int n_in,
                              void* d_out, int out_size) {
    const float* x    = (const float*)d_in[0];
    const float* xcov = (const float*)d_in[1];
    const int*   er   = (const int*)d_in[2];
    const int*   ec   = (const int*)d_in[3];
    const float* adjv = (const float*)d_in[4];
    const float* nv   = (const float*)d_in[5];
    const float* gam  = (const float*)d_in[6];
    const float* bet  = (const float*)d_in[7];
    const float* c0W1 = (const float*)d_in[8];
    const float* c0b1 = (const float*)d_in[9];
    const float* c0W2 = (const float*)d_in[10];
    const float* c0b2 = (const float*)d_in[11];
    const float* c1W1 = (const float*)d_in[12];
    const float* c1b1 = (const float*)d_in[13];
    const float* c1W2 = (const float*)d_in[14];
    const float* c1b2 = (const float*)d_in[15];
    // c2_* (d_in[16..19]) are dead code in the reference
    const float* mW1 = (const float*)d_in[20];
    const float* mb1 = (const float*)d_in[21];
    const float* a1  = (const float*)d_in[22];
    const float* mW2 = (const float*)d_in[23];
    const float* mb2 = (const float*)d_in[24];
    const float* a2  = (const float*)d_in[25];
    const float* mW3 = (const float*)d_in[26];
    const float* mb3 = (const float*)d_in[27];

    float* outLog = (float*)d_out;
    float* outAdj = (float*)d_out + (size_t)N_NODES * 2;

    GSYM(xp0, g_xp0)   GSYM(xp1, g_xp1)
    GSYM(hA,  g_hA)    GSYM(hB1, g_hB1)   GSYM(hB2, g_hB2)
    GSYM(S0,  g_S0)    GSYM(corr0, g_corr0)
    GSYM(cs0, g_cs0)   GSYM(cs1, g_cs1)
    GSYM(xc1, g_xc1)   GSYM(corr1, g_corr1) GSYM(T0, g_T0) GSYM(G0, g_G0)
    GSYM(S1,  g_S1)    GSYM(xc2, g_xc2)   GSYM(corr2, g_corr2)
    GSYM(T1,  g_T1)    GSYM(G1,  g_G1)    GSYM(P1,  g_P1)
    GSYM(pa1, g_pa1)   GSYM(pa2, g_pa2)   GSYM(pc1, g_pc1)
    GSYM(csA, g_csA)   GSYM(cssA, g_cssA)
    GSYM(csB, g_csB)   GSYM(qB, g_qB)
    GSYM(csC, g_csC)   GSYM(qC, g_qC)
    GSYM(pb1, g_pb1)   GSYM(pb2, g_pb2)
    GSYM(csX, g_csX)   GSYM(cssX, g_cssX)
    GSYM(tnp, g_tnpart) GSYM(tnp2, g_tnpart2)

    const int FUSED_SMEM = 77312;
    const int NN3_SMEM = 55296;
    cudaFuncSetAttribute(k_fused_mask, cudaFuncAttributeMaxDynamicSharedMemorySize,
                         FUSED_SMEM);
    cudaFuncSetAttribute(k_nn_mma3, cudaFuncAttributeMaxDynamicSharedMemorySize,
                         NN3_SMEM);

    cudaStream_t s2, s3;
    cudaStreamCreateWithFlags(&s2, cudaStreamNonBlocking);
    cudaStreamCreateWithFlags(&s3, cudaStreamNonBlocking);
    cudaEvent_t evFork, evJoin, evCorr0, evS0, evCs0, evS1, evP1;
    cudaEventCreateWithFlags(&evFork, cudaEventDisableTiming);
    cudaEventCreateWithFlags(&evJoin, cudaEventDisableTiming);
    cudaEventCreateWithFlags(&evCorr0, cudaEventDisableTiming);
    cudaEventCreateWithFlags(&evS0, cudaEventDisableTiming);
    cudaEventCreateWithFlags(&evCs0, cudaEventDisableTiming);
    cudaEventCreateWithFlags(&evS1, cudaEventDisableTiming);
    cudaEventCreateWithFlags(&evP1, cudaEventDisableTiming);

    k_zero<<<(N_NODES + 1023) / 1024, 1024>>>();
    cudaEventRecord(evFork, 0);
    cudaStreamWaitEvent(s2, evFork, 0);
    cudaStreamWaitEvent(s3, evFork, 0);

    // ============ chain B (s2): stats -> CSR -> prop(BN-fused) -> MLP -> outLog ===
    k_psum<<<250, 128, 0, s2>>>(x, N_NODES, FDIM, 32, pb1, pb2);
    k_preduce<<<1, 128, 0, s2>>>(pb1, pb2, 250, FDIM, N_NODES, csX, cssX);
    k_count<<<EDGES / 256, 256, 0, s2>>>(er);
    k_scan<<<1, 1024, 0, s2>>>();
    k_scatter<<<EDGES / 256, 256, 0, s2>>>(er, ec, nv);

    k_prop_bn<<<N_NODES / 2, 256, 0, s2>>>(x, csX, cssX, gam, bet, xp0);
    {
        const float* cur = xp0;
        float* bufs[2] = {xp1, xp0};
        for (int it = 0; it < 9; it++) {
            float* o = bufs[it & 1];
            k_prop<<<N_NODES / 2, 256, 0, s2>>>(cur, o);
            cur = o;
        }
        // ends in xp1
    }
    k_nn_mma3<<<dim3(63, 2), 256, NN3_SMEM, s2>>>(N_NODES, FDIM, xp1, mW1, mb1, hB1, 2, a1);
    k_nn_mma3<<<dim3(63, 2), 256, NN3_SMEM, s2>>>(N_NODES, FDIM, hB1, mW2, mb2, hB2, 2, a2);
    k_final<<<(N_NODES * 32 + 255) / 256, 256, 0, s2>>>(hB2, mW3, mb3, outLog);

    // ============ chain C part 1 (s3): corr0 ============
    k_psum<<<250, 128, 0, s3>>>(xcov, N_NODES, FDIM, 32, pa1, pa2);
    k_preduce<<<1, 128, 0, s3>>>(pa1, pa2, 250, FDIM, N_NODES, csA, cssA);
    k_corr<<<N_NODES, 128, 0, s3>>>(xcov, N_NODES, csA, cssA, corr0, 0, 0, 0);
    cudaEventRecord(evCorr0, s3);

    // ============ chain A (stream 0): cluster MLP -> softmax ============
    k_nn_mma3<<<dim3(63, 2), 256, NN3_SMEM>>>(N_NODES, FDIM, xcov, c0W1, c0b1, hA, 1, 0);
    k_nn_mma3<<<dim3(63, 7), 256, NN3_SMEM>>>(N_NODES, C0, hA, c0W2, c0b2, S0, 0, 0);
    k_softmax400<<<N_NODES, 128>>>(S0);
    cudaEventRecord(evS0, 0);

    // ============ chain C part 2 (s3): S0 colsum ============
    cudaStreamWaitEvent(s3, evS0, 0);
    k_psum<<<250, 128, 0, s3>>>(S0, N_NODES, C0, 32, pc1, 0);
    k_preduce<<<4, 128, 0, s3>>>(pc1, 0, 250, C0, N_NODES, cs0, 0);
    cudaEventRecord(evCs0, s3);

    // ============ chain A continues (stream 0) ============
    cudaStreamWaitEvent(0, evCorr0, 0);
    k_tn_mma<<<dim3(7, ZSPLIT), 256>>>(S0, xcov, corr0, tnp, tnp2);
    cudaStreamWaitEvent(0, evCs0, 0);
    k_tn_red2<<<(C0 * FDIM + 255) / 256, 256>>>(tnp, tnp2, ZSPLIT, C0, FDIM, cs0,
                                                xc1, T0, csB, qB);

    k_corr<<<C0, 128>>>(xc1, C0, csB, qB, corr1, T0, G0, 1);

    // level 1 cluster
    k_nn_mma3<<<dim3(4, 2), 256, NN3_SMEM>>>(C0, FDIM, xc1, c1W1, c1b1, hA, 1, 0);
    k_nn_mma3<<<dim3(4, 1), 256, NN3_SMEM>>>(C0, C1, hA, c1W2, c1b2, S1, 0, 0);
    k_softmax20<<<50, 256>>>(S1, cs1);
    cudaEventRecord(evS1, 0);

    // ============ chain C part 3 (s3): P1 = S0 @ S1 ============
    cudaStreamWaitEvent(s3, evS1, 0);
    k_gemm_nn<<<dim3(125, 1), 256, 0, s3>>>(N_NODES, C1, C0, S0, S1, 0, P1, 0, 0);
    cudaEventRecord(evP1, s3);

    // ============ chain A tail (stream 0): fused level-1 TN ============
    k_tn16<<<C1, 128>>>(S1, xc1, corr1, cs1, xc2, T1, csC, qC);
    k_corr<<<C1, 128>>>(xc2, C1, csC, qC, corr2, T1, G1, 1);

    cudaStreamWaitEvent(0, evP1, 0);
    k_fused_mask<<<EDGES / 128, 256, FUSED_SMEM>>>(S0, G0, P1, G1, er, ec, adjv, outAdj);

    // ============ join ============
    cudaEventRecord(evJoin, s2);
    cudaStreamWaitEvent(0, evJoin, 0);

    cudaEventDestroy(evFork);
    cudaEventDestroy(evJoin);
    cudaEventDestroy(evCorr0);
    cudaEventDestroy(evS0);
    cudaEventDestroy(evCs0);
    cudaEventDestroy(evS1);
    cudaEventDestroy(evP1);
    cudaStreamDestroy(s2);
    cudaStreamDestroy(s3);

    (void)in_sizes; (void)n_in; (void)out_size;
}

// round 17
// speedup vs baseline: 1.4131x; 1.3460x over previous
#include <cuda_runtime.h>
#include <cuda_fp16.h>
#include <math.h>

#define N_NODES 8000
#define FDIM    128
#define EDGES   256000
#define C0      400
#define C1      20
#define ZSPLIT  25

// ---------------- static device scratch (no runtime allocation) ----------------
__device__ float g_xp0[N_NODES*FDIM];
__device__ float g_xp1[N_NODES*FDIM];
__device__ float g_hA [N_NODES*FDIM];
__device__ float g_hB1[N_NODES*FDIM];
__device__ float g_hB2[N_NODES*FDIM];
__device__ float g_S0 [N_NODES*C0];
__device__ float g_corr0[N_NODES*FDIM];
__device__ float g_cs0[C0];
__device__ float g_cs1[C1];
__device__ float g_xc1  [C0*FDIM];
__device__ float g_corr1[C0*FDIM];
__device__ float g_T0   [C0*FDIM];
__device__ float g_G0   [C0*FDIM];
__device__ float g_S1   [C0*C1];
__device__ float g_xc2  [C1*FDIM];
__device__ float g_corr2[C1*FDIM];
__device__ float g_T1   [C1*FDIM];
__device__ float g_G1   [C1*FDIM];
__device__ float g_P1   [N_NODES*C1];
__device__ float g_pa1[250*C0];
__device__ float g_pa2[250*C0];
__device__ float g_pc1[250*C0];
__device__ float g_csA[FDIM];
__device__ float g_cssA[FDIM];
__device__ float g_csB[FDIM];
__device__ float g_qB [FDIM];
__device__ float g_csC[FDIM];
__device__ float g_qC [FDIM];
__device__ float g_pb1[250*FDIM];
__device__ float g_pb2[250*FDIM];
__device__ float g_csX[FDIM];
__device__ float g_cssX[FDIM];
__device__ float g_tnpart [ZSPLIT*C0*FDIM];
__device__ float g_tnpart2[ZSPLIT*C0*FDIM];
__device__ int   g_cnt[N_NODES];
__device__ int   g_off[N_NODES+1];
__device__ int   g_cur[N_NODES];
__device__ float2 g_ePk[EDGES];   // packed (col-as-float-bits, weight)

// ---------------- zero all atomic-accumulated buffers + cnt (one launch) --------
__global__ void k_zero() {
    int i = blockIdx.x * blockDim.x + threadIdx.x;
    if (i < N_NODES) g_cnt[i] = 0;
    if (i < FDIM) { g_csB[i] = 0.f; g_qB[i] = 0.f; g_csC[i] = 0.f; g_qC[i] = 0.f; }
    if (i < C1) g_cs1[i] = 0.f;
}

// ---------------- two-stage deterministic column stats ----------------
__global__ void k_psum(const float* __restrict__ A, int n, int c, int rowsPer,
                       float* __restrict__ ps, float* __restrict__ pq) {
    int b = blockIdx.x;
    int r0 = b * rowsPer, r1 = min(n, r0 + rowsPer);
    for (int col = threadIdx.x; col < c; col += blockDim.x) {
        float s = 0.f, q = 0.f;
        for (int r = r0; r < r1; r++) {
            float v = A[(size_t)r * c + col];
            s += v; q += v * v;
        }
        ps[(size_t)b * c + col] = s;
        if (pq) pq[(size_t)b * c + col] = q;
    }
}

__global__ void k_preduce(const float* __restrict__ ps, const float* __restrict__ pq,
                          int nb, int c, int n,
                          float* __restrict__ outS, float* __restrict__ outCss) {
    int col = blockIdx.x * blockDim.x + threadIdx.x;
    if (col >= c) return;
    float s = 0.f, q = 0.f;
    for (int b = 0; b < nb; b++) {
        s += ps[(size_t)b * c + col];
        if (pq) q += pq[(size_t)b * c + col];
    }
    outS[col] = s;
    if (outCss) outCss[col] = q - s * s / (float)n;
}

// ---------------- node correlation (+ optional fused gains) ----------------
__global__ void k_corr(const float* __restrict__ z, int n,
                       const float* __restrict__ cs, const float* __restrict__ cssOrQ,
                       float* __restrict__ out,
                       const float* __restrict__ T, float* __restrict__ G, int rawq) {
    int r = blockIdx.x, f = threadIdx.x;
    float s = cs[f];
    float mean = s / (float)n;
    float css = rawq ? (cssOrQ[f] - s * s / (float)n) : cssOrQ[f];
    float inv = 1.f / (sqrtf(css) + 1e-12f);
    float v = (z[(size_t)r * FDIM + f] - mean) * inv;
    __shared__ float red[128];
    red[f] = v; __syncthreads();
    for (int st = 64; st > 0; st >>= 1) {
        if (f < st) red[f] += red[f + st];
        __syncthreads();
    }
    size_t idx = (size_t)r * FDIM + f;
    float cv = v * red[0];
    out[idx] = cv;
    if (T) {
        float x = 1.f / (1.f + expf(T[idx] - cv));
        G[idx] = x * x;
    }
}

// ---------------- softmax for S0 rows (W=400), register-resident ----------------
__global__ void k_softmax400(float* __restrict__ X) {
    int r = blockIdx.x;
    float* row = X + (size_t)r * C0;
    int t = threadIdx.x;
    int cnt = (t < C0 - 3 * 128) ? 4 : 3;
    float v[4];
    float m = -3.4e38f;
#pragma unroll
    for (int j = 0; j < 4; j++) {
        if (j < cnt) { v[j] = row[t + 128 * j]; m = fmaxf(m, v[j]); }
    }
    __shared__ float red[128];
    red[t] = m; __syncthreads();
    for (int s = 64; s > 0; s >>= 1) {
        if (t < s) red[t] = fmaxf(red[t], red[t + s]);
        __syncthreads();
    }
    m = red[0]; __syncthreads();
    float sum = 0.f;
#pragma unroll
    for (int j = 0; j < 4; j++) {
        if (j < cnt) { v[j] = expf(v[j] - m); sum += v[j]; }
    }
    red[t] = sum; __syncthreads();
    for (int s = 64; s > 0; s >>= 1) {
        if (t < s) red[t] += red[t + s];
        __syncthreads();
    }
    float inv = 1.f / red[0];
#pragma unroll
    for (int j = 0; j < 4; j++) {
        if (j < cnt) row[t + 128 * j] = v[j] * inv;
    }
}

// ---------------- softmax for S1 rows (W=20), warp/row + fused colsum ----------
__global__ void k_softmax20(float* __restrict__ X, float* __restrict__ cs) {
    int warp = (blockIdx.x * blockDim.x + threadIdx.x) >> 5;
    int lane = threadIdx.x & 31;
    if (warp >= C0) return;
    float* row = X + (size_t)warp * C1;
    float v = (lane < C1) ? row[lane] : -3.4e38f;
    float m = v;
#pragma unroll
    for (int o = 16; o; o >>= 1) m = fmaxf(m, __shfl_xor_sync(0xFFFFFFFFu, m, o));
    float e = (lane < C1) ? expf(v - m) : 0.f;
    float s = e;
#pragma unroll
    for (int o = 16; o; o >>= 1) s += __shfl_xor_sync(0xFFFFFFFFu, s, o);
    if (lane < C1) {
        float val = e / s;
        row[lane] = val;
        atomicAdd(&cs[lane], val);
    }
}

// ---------------- tf32 helper ----------------
__device__ __forceinline__ unsigned tf32r(float x) {
    unsigned u;
    asm("cvt.rna.tf32.f32 %0, %1;" : "=r"(u) : "f"(x));
    return u;
}

#define MMA_TF32(ACC, A0, A1, A2, A3, B0, B1)                                  \
    asm volatile(                                                              \
        "mma.sync.aligned.m16n8k8.row.col.f32.tf32.tf32.f32 "                  \
        "{%0,%1,%2,%3}, {%4,%5,%6,%7}, {%8,%9}, {%0,%1,%2,%3};"                \
        : "+f"(ACC[0]), "+f"(ACC[1]), "+f"(ACC[2]), "+f"(ACC[3])               \
        : "r"(A0), "r"(A1), "r"(A2), "r"(A3), "r"(B0), "r"(B1))

#define MMA_F16(ACC, A0, A1, A2, A3, B0, B1)                                   \
    asm volatile(                                                              \
        "mma.sync.aligned.m16n8k16.row.col.f32.f16.f16.f32 "                   \
        "{%0,%1,%2,%3}, {%4,%5,%6,%7}, {%8,%9}, {%0,%1,%2,%3};"                \
        : "+f"(ACC[0]), "+f"(ACC[1]), "+f"(ACC[2]), "+f"(ACC[3])               \
        : "r"(A0), "r"(A1), "r"(A2), "r"(A3), "r"(B0), "r"(B1))

// ---------------- split-3 tf32 NN GEMM (fp32-accurate): C = act(A@B + bias) -----
__global__ void __launch_bounds__(256)
k_nn_mma3(int M, int N,
          const float* __restrict__ A, const float* __restrict__ B,
          const float* __restrict__ bias, float* __restrict__ C,
          int act, const float* __restrict__ aux) {
    extern __shared__ __align__(16) char sm3[];
    unsigned (*Ah)[36] = (unsigned(*)[36])(sm3);
    unsigned (*Al)[36] = (unsigned(*)[36])(sm3 + 18432);
    unsigned (*Bh)[72] = (unsigned(*)[72])(sm3 + 36864);
    unsigned (*Bl)[72] = (unsigned(*)[72])(sm3 + 46080);
    int t = threadIdx.x, lane = t & 31, w = t >> 5;
    int m0 = blockIdx.x * 128, n0 = blockIdx.y * 64;
    float acc[8][4];
#pragma unroll
    for (int nt = 0; nt < 8; nt++)
#pragma unroll
        for (int i = 0; i < 4; i++) acc[nt][i] = 0.f;

    for (int k0 = 0; k0 < 128; k0 += 32) {
        for (int idx = t; idx < 128 * 32; idx += 256) {
            int r = idx >> 5, kk = idx & 31;
            int row = m0 + r;
            float v = (row < M) ? A[(size_t)row * 128 + k0 + kk] : 0.f;
            unsigned h = tf32r(v);
            Ah[r][kk] = h;
            Al[r][kk] = tf32r(v - __uint_as_float(h));
        }
        for (int idx = t; idx < 32 * 64; idx += 256) {
            int kk = idx >> 6, n = idx & 63;
            int col = n0 + n;
            float v = (col < N) ? B[(size_t)(k0 + kk) * N + col] : 0.f;
            unsigned h = tf32r(v);
            Bh[kk][n] = h;
            Bl[kk][n] = tf32r(v - __uint_as_float(h));
        }
        __syncthreads();
#pragma unroll
        for (int ks = 0; ks < 4; ks++) {
            int kb = ks * 8;
            int ar = w * 16 + (lane >> 2);
            int ak = kb + (lane & 3);
            unsigned ah0 = Ah[ar][ak],     ah1 = Ah[ar + 8][ak];
            unsigned ah2 = Ah[ar][ak + 4], ah3 = Ah[ar + 8][ak + 4];
            unsigned al0 = Al[ar][ak],     al1 = Al[ar + 8][ak];
            unsigned al2 = Al[ar][ak + 4], al3 = Al[ar + 8][ak + 4];
#pragma unroll
            for (int nt = 0; nt < 8; nt++) {
                int bn = nt * 8 + (lane >> 2);
                unsigned bh0 = Bh[kb + (lane & 3)][bn];
                unsigned bh1 = Bh[kb + (lane & 3) + 4][bn];
                unsigned bl0 = Bl[kb + (lane & 3)][bn];
                unsigned bl1 = Bl[kb + (lane & 3) + 4][bn];
                MMA_TF32(acc[nt], ah0, ah1, ah2, ah3, bh0, bh1);
                MMA_TF32(acc[nt], ah0, ah1, ah2, ah3, bl0, bl1);
                MMA_TF32(acc[nt], al0, al1, al2, al3, bh0, bh1);
            }
        }
        __syncthreads();
    }
    float slope = (act == 2) ? aux[0] : 0.f;
    int rbase = m0 + w * 16 + (lane >> 2);
#pragma unroll
    for (int nt = 0; nt < 8; nt++) {
        int cb = n0 + nt * 8 + 2 * (lane & 3);
#pragma unroll
        for (int q = 0; q < 4; q++) {
            int r = rbase + ((q >= 2) ? 8 : 0);
            int c = cb + (q & 1);
            if (r < M && c < N) {
                float v = acc[nt][q];
                if (bias) v += bias[c];
                if (act == 1) v = fmaxf(v, 0.f);
                else if (act == 2) v = (v >= 0.f) ? v : slope * v;
                C[(size_t)r * N + c] = v;
            }
        }
    }
}

// ---------------- generic tiled SIMT GEMM (small uses) ----------------
__global__ void k_gemm_nn(int M, int N, int K,
                          const float* __restrict__ A, const float* __restrict__ B,
                          const float* __restrict__ bias, float* __restrict__ C,
                          int act, const float* __restrict__ aux) {
    __shared__ __align__(16) float As[16][68];
    __shared__ __align__(16) float Bs[16][64];
    int t = threadIdx.x;
    int m0 = blockIdx.x * 64, n0 = blockIdx.y * 64;
    int tx = t & 15, ty = t >> 4;
    float acc[4][4];
#pragma unroll
    for (int i = 0; i < 4; i++)
#pragma unroll
        for (int j = 0; j < 4; j++) acc[i][j] = 0.f;
    for (int k0 = 0; k0 < K; k0 += 16) {
        __syncthreads();
        for (int idx = t; idx < 1024; idx += 256) {
            int kk = idx & 15, r = idx >> 4;
            int row = m0 + r;
            As[kk][r] = (row < M) ? A[(size_t)row * K + k0 + kk] : 0.f;
        }
        for (int idx = t; idx < 1024; idx += 256) {
            int kk = idx >> 6, c = idx & 63;
            int col = n0 + c;
            Bs[kk][c] = (col < N) ? B[(size_t)(k0 + kk) * N + col] : 0.f;
        }
        __syncthreads();
#pragma unroll
        for (int kk = 0; kk < 16; kk++) {
            float4 av = *(const float4*)&As[kk][ty * 4];
            float4 bv = *(const float4*)&Bs[kk][tx * 4];
            float a4[4] = {av.x, av.y, av.z, av.w};
            float b4[4] = {bv.x, bv.y, bv.z, bv.w};
#pragma unroll
            for (int i = 0; i < 4; i++)
#pragma unroll
                for (int j = 0; j < 4; j++) acc[i][j] += a4[i] * b4[j];
        }
    }
    float slope = (act == 2) ? aux[0] : 0.f;
#pragma unroll
    for (int i = 0; i < 4; i++) {
        int row = m0 + ty * 4 + i;
        if (row >= M) continue;
#pragma unroll
        for (int j = 0; j < 4; j++) {
            int col = n0 + tx * 4 + j;
            if (col >= N) continue;
            float v = acc[i][j];
            if (bias) v += bias[col];
            if (act == 1) v = fmaxf(v, 0.f);
            else if (act == 2) v = (v >= 0.f) ? v : slope * v;
            C[(size_t)row * N + col] = v;
        }
    }
}

// ---------------- tf32 MMA TN GEMM (split-m) ----------------
__global__ void __launch_bounds__(256)
k_tn_mma(const float* __restrict__ A,
         const float* __restrict__ B1, const float* __restrict__ B2,
         float* __restrict__ part1, float* __restrict__ part2) {
    __shared__ unsigned As[64][33];
    __shared__ unsigned Bs1[32][136];
    __shared__ unsigned Bs2[32][136];
    int t = threadIdx.x, lane = t & 31, w = t >> 5;
    int wr = w & 3, wc = w >> 2;
    int k10 = blockIdx.x * 64;
    int mBase = blockIdx.y * 320;
    float acc1[8][4], acc2[8][4];
#pragma unroll
    for (int nt = 0; nt < 8; nt++)
#pragma unroll
        for (int i = 0; i < 4; i++) { acc1[nt][i] = 0.f; acc2[nt][i] = 0.f; }

    for (int mc = 0; mc < 320; mc += 32) {
        for (int idx = t; idx < 2048; idx += 256) {
            int m = idx >> 6, kl = idx & 63;
            int k1 = k10 + kl;
            float v = (k1 < C0) ? A[(size_t)(mBase + mc + m) * C0 + k1] : 0.f;
            As[kl][m] = tf32r(v);
        }
        for (int idx = t; idx < 4096; idx += 256) {
            int m = idx >> 7, n = idx & 127;
            size_t g = (size_t)(mBase + mc + m) * FDIM + n;
            Bs1[m][n] = tf32r(B1[g]);
            Bs2[m][n] = tf32r(B2[g]);
        }
        __syncthreads();
#pragma unroll
        for (int ks = 0; ks < 4; ks++) {
            int ar = wr * 16 + (lane >> 2);
            int ak = ks * 8 + (lane & 3);
            unsigned a0 = As[ar][ak];
            unsigned a1 = As[ar + 8][ak];
            unsigned a2 = As[ar][ak + 4];
            unsigned a3 = As[ar + 8][ak + 4];
#pragma unroll
            for (int nt = 0; nt < 8; nt++) {
                int bn = wc * 64 + nt * 8 + (lane >> 2);
                unsigned b0 = Bs1[ks * 8 + (lane & 3)][bn];
                unsigned b1 = Bs1[ks * 8 + (lane & 3) + 4][bn];
                MMA_TF32(acc1[nt], a0, a1, a2, a3, b0, b1);
                unsigned c0 = Bs2[ks * 8 + (lane & 3)][bn];
                unsigned c1 = Bs2[ks * 8 + (lane & 3) + 4][bn];
                MMA_TF32(acc2[nt], a0, a1, a2, a3, c0, c1);
            }
        }
        __syncthreads();
    }
    int z = blockIdx.y;
    int k1r = k10 + wr * 16 + (lane >> 2);
    int cb = 2 * (lane & 3);
#pragma unroll
    for (int nt = 0; nt < 8; nt++) {
        int n = wc * 64 + nt * 8 + cb;
        if (k1r < C0) {
            size_t b = ((size_t)z * C0 + k1r) * FDIM + n;
            part1[b] = acc1[nt][0]; part1[b + 1] = acc1[nt][1];
            part2[b] = acc2[nt][0]; part2[b + 1] = acc2[nt][1];
        }
        if (k1r + 8 < C0) {
            size_t b = ((size_t)z * C0 + k1r + 8) * FDIM + n;
            part1[b] = acc1[nt][2]; part1[b + 1] = acc1[nt][3];
            part2[b] = acc2[nt][2]; part2[b + 1] = acc2[nt][3];
        }
    }
}

// dual reduce + fused atomic column-stats of out1 (if csS!=0)
__global__ void k_tn_red2(const float* __restrict__ part1, const float* __restrict__ part2,
                          int S, int K1, int N,
                          const float* __restrict__ divrow,
                          float* __restrict__ out1, float* __restrict__ out2,
                          float* __restrict__ csS, float* __restrict__ qS) {
    int i = blockIdx.x * blockDim.x + threadIdx.x;
    if (i >= K1 * N) return;
    float s1 = 0.f, s2 = 0.f;
    for (int b = 0; b < S; b++) {
        s1 += part1[(size_t)b * K1 * N + i];
        s2 += part2[(size_t)b * K1 * N + i];
    }
    if (divrow) s1 /= (divrow[i / N] + 1e-12f);
    out1[i] = s1;
    out2[i] = s2;
    if (csS) {
        int f = i % N;
        atomicAdd(&csS[f], s1);
        atomicAdd(&qS[f], s1 * s1);
    }
}

// ---------------- fused level-1 TN: xc2 = S1^T@xc1/cs1, T1 = S1^T@corr1 ----------
__global__ void k_tn16(const float* __restrict__ S1,
                       const float* __restrict__ B1, const float* __restrict__ B2,
                       const float* __restrict__ cs1,
                       float* __restrict__ out1, float* __restrict__ out2,
                       float* __restrict__ csS, float* __restrict__ qS) {
    int k1 = blockIdx.x, f = threadIdx.x;
    float a1 = 0.f, a2 = 0.f;
    for (int m = 0; m < C0; m++) {
        float s = S1[m * C1 + k1];
        a1 += s * B1[(size_t)m * FDIM + f];
        a2 += s * B2[(size_t)m * FDIM + f];
    }
    float o1 = a1 / (cs1[k1] + 1e-12f);
    out1[(size_t)k1 * FDIM + f] = o1;
    out2[(size_t)k1 * FDIM + f] = a2;
    atomicAdd(&csS[f], o1);
    atomicAdd(&qS[f], o1 * o1);
}

// ---------------- FUSED: mask(K=400 fp16 MMA) + mask(K=20) + serial carry --------
// smem 77312 B -> 2 CTA/SM:
//  phase1 alias: Us16[128][18] u32 @0 (9216), Gs16[16][136] u32 @9216 (8704)
//  phase2 alias: Ms[128][129] f32 @0 (66048)
//  persistent:   G1s[20][128] @66048 (10240), rr @76288 (512), cc @76800 (512)
__global__ void __launch_bounds__(256, 2)
k_fused_mask(const float* __restrict__ s0p, const float* __restrict__ g0sq,
             const float* __restrict__ p1, const float* __restrict__ g1sq,
             const int* __restrict__ er, const int* __restrict__ ec,
             const float* __restrict__ adjv, float* __restrict__ outAdj) {
    extern __shared__ __align__(16) char sm[];
    unsigned (*Us16)[18]  = (unsigned(*)[18])(sm);
    unsigned (*Gs16)[136] = (unsigned(*)[136])(sm + 9216);
    float (*Ms)[129]      = (float(*)[129])(sm);
    float (*G1s)[128]     = (float(*)[128])(sm + 66048);
    int* rr               = (int*)(sm + 76288);
    int* cc               = (int*)(sm + 76800);

    int t = threadIdx.x, lane = t & 31, w = t >> 5;
    int e0 = blockIdx.x * 128;
    if (t < 128) { rr[t] = er[e0 + t]; cc[t] = ec[e0 + t]; }
    for (int idx = t; idx < C1 * FDIM; idx += 256)
        G1s[idx >> 7][idx & 127] = g1sq[idx];
    float acc[16][4];
#pragma unroll
    for (int nt = 0; nt < 16; nt++)
#pragma unroll
        for (int i = 0; i < 4; i++) acc[nt][i] = 0.f;
    __syncthreads();

    // ---- phase 1: mB via fp16 MMA over K=400 (13 chunks of 32) ----
    for (int k0 = 0; k0 < C0; k0 += 32) {
        // stage G chunk: 16 half2-rows x 128 f
        for (int idx = t; idx < 16 * 128; idx += 256) {
            int j = idx >> 7, f = idx & 127;
            int k = k0 + 2 * j;
            float gg0 = 0.f, gg1 = 0.f;
            if (k < C0) {
                gg0 = g0sq[(size_t)k * FDIM + f];
                gg1 = g0sq[(size_t)(k + 1) * FDIM + f];
            }
            __half2 h = __floats2half2_rn(gg0, gg1);
            Gs16[j][f] = *(unsigned*)&h;
        }
        // stage U chunk: 128 edges x 16 half2 (aligned float2 gmem loads)
        for (int idx = t; idx < 128 * 16; idx += 256) {
            int e = idx >> 4, j = idx & 15;
            int k = k0 + 2 * j;
            float u0 = 0.f, u1 = 0.f;
            if (k < C0) {
                float2 srr = *(const float2*)&s0p[(size_t)rr[e] * C0 + k];
                float2 scc = *(const float2*)&s0p[(size_t)cc[e] * C0 + k];
                u0 = srr.x * scc.x;
                u1 = srr.y * scc.y;
            }
            __half2 h = __floats2half2_rn(u0, u1);
            Us16[e][j] = *(unsigned*)&h;
        }
        __syncthreads();
#pragma unroll
        for (int ks = 0; ks < 2; ks++) {
            int ar = w * 16 + (lane >> 2);
            int aj = ks * 8 + (lane & 3);
            unsigned a0 = Us16[ar][aj];
            unsigned a1 = Us16[ar + 8][aj];
            unsigned a2 = Us16[ar][aj + 4];
            unsigned a3 = Us16[ar + 8][aj + 4];
#pragma unroll
            for (int nt = 0; nt < 16; nt++) {
                int bn = nt * 8 + (lane >> 2);
                unsigned b0 = Gs16[aj][bn];
                unsigned b1 = Gs16[aj + 4][bn];
                MMA_F16(acc[nt], a0, a1, a2, a3, b0, b1);
            }
        }
        __syncthreads();
    }
    // ---- epilogue: acc -> Ms[f][e] ----
    {
        int r = w * 16 + (lane >> 2);
        int cb = 2 * (lane & 3);
#pragma unroll
        for (int nt = 0; nt < 16; nt++) {
            int c = nt * 8 + cb;
            Ms[c][r]         = acc[nt][0];
            Ms[c + 1][r]     = acc[nt][1];
            Ms[c][r + 8]     = acc[nt][2];
            Ms[c + 1][r + 8] = acc[nt][3];
        }
    }
    __syncthreads();
    // ---- phase 2: serial carry, thread = edge ----
    if (t < 128) {
        int e = t;
        float u20[C1];
        const float* pr = p1 + (size_t)rr[e] * C1;
        const float* pc = p1 + (size_t)cc[e] * C1;
#pragma unroll
        for (int k = 0; k < C1; k++) u20[k] = pr[k] * pc[k];
        float a = adjv[e0 + e];
        for (int f = 0; f < FDIM; f++) {
            float mA = 0.f;
#pragma unroll
            for (int k = 0; k < C1; k++) mA += u20[k] * G1s[k][f];
            float mB = Ms[f][e];
            float tq = a * mA;
            outAdj[(size_t)f * EDGES + e0 + e] = tq + tq * mB;
            a = tq * mB;
        }
    }
}

// ---------------- CSR build ----------------
__global__ void k_count(const int* __restrict__ er) {
    int e = blockIdx.x * blockDim.x + threadIdx.x;
    if (e < EDGES) atomicAdd(&g_cnt[er[e]], 1);
}

__global__ void k_scan() {
    __shared__ int part[1024];
    const int n = N_NODES;
    const int per = (n + 1023) / 1024;
    int t = threadIdx.x;
    int s = 0;
    int lo = t * per, hi = min(n, (t + 1) * per);
    for (int i = lo; i < hi; i++) s += g_cnt[i];
    part[t] = s; __syncthreads();
    for (int off = 1; off < 1024; off <<= 1) {
        int v = (t >= off) ? part[t - off] : 0;
        __syncthreads();
        part[t] += v;
        __syncthreads();
    }
    int base = (t == 0) ? 0 : part[t - 1];
    for (int i = lo; i < hi; i++) {
        g_off[i] = base; g_cur[i] = base; base += g_cnt[i];
    }
    if (t == 1023) g_off[n] = base;
}

__global__ void k_scatter(const int* __restrict__ er, const int* __restrict__ ec,
                          const float* __restrict__ nv) {
    int e = blockIdx.x * blockDim.x + threadIdx.x;
    if (e < EDGES) {
        int pos = atomicAdd(&g_cur[er[e]], 1);
        g_ePk[pos] = make_float2(__int_as_float(ec[e]), nv[e]);
    }
}

// ---------------- propagation step with fused BN (packed edges) ----------------
__global__ void k_prop_bn(const float* __restrict__ x,
                          const float* __restrict__ cs, const float* __restrict__ css,
                          const float* __restrict__ gam, const float* __restrict__ bet,
                          float* __restrict__ xout) {
    int r = blockIdx.x * 2 + (threadIdx.x >> 7);
    int f = threadIdx.x & 127;
    float mu   = cs[f]  * (1.f / N_NODES);
    float var  = css[f] * (1.f / N_NODES);
    float rstd = rsqrtf(var + 1e-5f);
    float scale = gam[f] * rstd;
    float shift = bet[f] - mu * scale;
    float acc = 0.f;
    int s = g_off[r], e = g_off[r + 1];
    for (int i = s; i < e; i++) {
        float2 pk = g_ePk[i];
        int c = __float_as_int(pk.x);
        acc += pk.y * (x[(size_t)c * FDIM + f] * scale + shift);
    }
    xout[(size_t)r * FDIM + f] = acc;
}

// ---------------- plain propagation step (packed edges, 2 nodes/block) ----------
__global__ void k_prop(const float* __restrict__ xin, float* __restrict__ xout) {
    int r = blockIdx.x * 2 + (threadIdx.x >> 7);
    int f = threadIdx.x & 127;
    float acc = 0.f;
    int s = g_off[r], e = g_off[r + 1];
    for (int i = s; i < e; i++) {
        float2 pk = g_ePk[i];
        int c = __float_as_int(pk.x);
        acc += pk.y * xin[(size_t)c * FDIM + f];
    }
    xout[(size_t)r * FDIM + f] = acc;
}

// ---------------- final logits + log_softmax ----------------
__global__ void k_final(const float* __restrict__ h, const float* __restrict__ W,
                        const float* __restrict__ b, float* __restrict__ out) {
    int warp = (blockIdx.x * blockDim.x + threadIdx.x) >> 5;
    int lane = threadIdx.x & 31;
    if (warp >= N_NODES) return;
    float p0 = 0.f, p1 = 0.f;
#pragma unroll
    for (int j = 0; j < 4; j++) {
        int k = lane + 32 * j;
        float hv = h[(size_t)warp * FDIM + k];
        p0 += hv * W[k * 2];
        p1 += hv * W[k * 2 + 1];
    }
    for (int o = 16; o; o >>= 1) {
        p0 += __shfl_down_sync(0xFFFFFFFFu, p0, o);
        p1 += __shfl_down_sync(0xFFFFFFFFu, p1, o);
    }
    if (lane == 0) {
        float l0 = p0 + b[0], l1 = p1 + b[1];
        float m = fmaxf(l0, l1);
        float ls = m + logf(expf(l0 - m) + expf(l1 - m));
        out[warp * 2]     = l0 - ls;
        out[warp * 2 + 1] = l1 - ls;
    }
}

// ================= host launcher =================
#define GSYM(var, sym) float* var; { void* _p = 0; cudaGetSymbolAddress(&_p, sym); var = (float*)_p; }

extern "C" void kernel_launch(void* const* d_in, const int* in_sizes, int n_in,
                              void* d_out, int out_size) {
    const float* x    = (const float*)d_in[0];
    const float* xcov = (const float*)d_in[1];
    const int*   er   = (const int*)d_in[2];
    const int*   ec   = (const int*)d_in[3];
    const float* adjv = (const float*)d_in[4];
    const float* nv   = (const float*)d_in[5];
    const float* gam  = (const float*)d_in[6];
    const float* bet  = (const float*)d_in[7];
    const float* c0W1 = (const float*)d_in[8];
    const float* c0b1 = (const float*)d_in[9];
    const float* c0W2 = (const float*)d_in[10];
    const float* c0b2 = (const float*)d_in[11];
    const float* c1W1 = (const float*)d_in[12];
    const float* c1b1 = (const float*)d_in[13];
    const float* c1W2 = (const float*)d_in[14];
    const float* c1b2 = (const float*)d_in[15];
    // c2_* (d_in[16..19]) are dead code in the reference
    const float* mW1 = (const float*)d_in[20];
    const float* mb1 = (const float*)d_in[21];
    const float* a1  = (const float*)d_in[22];
    const float* mW2 = (const float*)d_in[23];
    const float* mb2 = (const float*)d_in[24];
    const float* a2  = (const float*)d_in[25];
    const float* mW3 = (const float*)d_in[26];
    const float* mb3 = (const float*)d_in[27];

    float* outLog = (float*)d_out;
    float* outAdj = (float*)d_out + (size_t)N_NODES * 2;

    GSYM(xp0, g_xp0)   GSYM(xp1, g_xp1)
    GSYM(hA,  g_hA)    GSYM(hB1, g_hB1)   GSYM(hB2, g_hB2)
    GSYM(S0,  g_S0)    GSYM(corr0, g_corr0)
    GSYM(cs0, g_cs0)   GSYM(cs1, g_cs1)
    GSYM(xc1, g_xc1)   GSYM(corr1, g_corr1) GSYM(T0, g_T0) GSYM(G0, g_G0)
    GSYM(S1,  g_S1)    GSYM(xc2, g_xc2)   GSYM(corr2, g_corr2)
    GSYM(T1,  g_T1)    GSYM(G1,  g_G1)    GSYM(P1,  g_P1)
    GSYM(pa1, g_pa1)   GSYM(pa2, g_pa2)   GSYM(pc1, g_pc1)
    GSYM(csA, g_csA)   GSYM(cssA, g_cssA)
    GSYM(csB, g_csB)   GSYM(qB, g_qB)
    GSYM(csC, g_csC)   GSYM(qC, g_qC)
    GSYM(pb1, g_pb1)   GSYM(pb2, g_pb2)
    GSYM(csX, g_csX)   GSYM(cssX, g_cssX)
    GSYM(tnp, g_tnpart) GSYM(tnp2, g_tnpart2)

    const int FUSED_SMEM = 77312;
    const int NN3_SMEM = 55296;
    cudaFuncSetAttribute(k_fused_mask, cudaFuncAttributeMaxDynamicSharedMemorySize,
                         FUSED_SMEM);
    cudaFuncSetAttribute(k_nn_mma3, cudaFuncAttributeMaxDynamicSharedMemorySize,
                         NN3_SMEM);

    cudaStream_t s2, s3;
    cudaStreamCreateWithFlags(&s2, cudaStreamNonBlocking);
    cudaStreamCreateWithFlags(&s3, cudaStreamNonBlocking);
    cudaEvent_t evFork, evJoin, evCorr0, evS0, evCs0, evS1, evP1;
    cudaEventCreateWithFlags(&evFork, cudaEventDisableTiming);
    cudaEventCreateWithFlags(&evJoin, cudaEventDisableTiming);
    cudaEventCreateWithFlags(&evCorr0, cudaEventDisableTiming);
    cudaEventCreateWithFlags(&evS0, cudaEventDisableTiming);
    cudaEventCreateWithFlags(&evCs0, cudaEventDisableTiming);
    cudaEventCreateWithFlags(&evS1, cudaEventDisableTiming);
    cudaEventCreateWithFlags(&evP1, cudaEventDisableTiming);

    k_zero<<<(N_NODES + 1023) / 1024, 1024>>>();
    cudaEventRecord(evFork, 0);
    cudaStreamWaitEvent(s2, evFork, 0);
    cudaStreamWaitEvent(s3, evFork, 0);

    // ============ chain B (s2): stats -> CSR -> prop(BN-fused) -> MLP -> outLog ===
    k_psum<<<250, 128, 0, s2>>>(x, N_NODES, FDIM, 32, pb1, pb2);
    k_preduce<<<1, 128, 0, s2>>>(pb1, pb2, 250, FDIM, N_NODES, csX, cssX);
    k_count<<<EDGES / 256, 256, 0, s2>>>(er);
    k_scan<<<1, 1024, 0, s2>>>();
    k_scatter<<<EDGES / 256, 256, 0, s2>>>(er, ec, nv);

    k_prop_bn<<<N_NODES / 2, 256, 0, s2>>>(x, csX, cssX, gam, bet, xp0);
    {
        const float* cur = xp0;
        float* bufs[2] = {xp1, xp0};
        for (int it = 0; it < 9; it++) {
            float* o = bufs[it & 1];
            k_prop<<<N_NODES / 2, 256, 0, s2>>>(cur, o);
            cur = o;
        }
        // ends in xp1
    }
    k_nn_mma3<<<dim3(63, 2), 256, NN3_SMEM, s2>>>(N_NODES, FDIM, xp1, mW1, mb1, hB1, 2, a1);
    k_nn_mma3<<<dim3(63, 2), 256, NN3_SMEM, s2>>>(N_NODES, FDIM, hB1, mW2, mb2, hB2, 2, a2);
    k_final<<<(N_NODES * 32 + 255) / 256, 256, 0, s2>>>(hB2, mW3, mb3, outLog);

    // ============ chain C part 1 (s3): corr0 ============
    k_psum<<<250, 128, 0, s3>>>(xcov, N_NODES, FDIM, 32, pa1, pa2);
    k_preduce<<<1, 128, 0, s3>>>(pa1, pa2, 250, FDIM, N_NODES, csA, cssA);
    k_corr<<<N_NODES, 128, 0, s3>>>(xcov, N_NODES, csA, cssA, corr0, 0, 0, 0);
    cudaEventRecord(evCorr0, s3);

    // ============ chain A (stream 0): cluster MLP -> softmax ============
    k_nn_mma3<<<dim3(63, 2), 256, NN3_SMEM>>>(N_NODES, FDIM, xcov, c0W1, c0b1, hA, 1, 0);
    k_nn_mma3<<<dim3(63, 7), 256, NN3_SMEM>>>(N_NODES, C0, hA, c0W2, c0b2, S0, 0, 0);
    k_softmax400<<<N_NODES, 128>>>(S0);
    cudaEventRecord(evS0, 0);

    // ============ chain C part 2 (s3): S0 colsum ============
    cudaStreamWaitEvent(s3, evS0, 0);
    k_psum<<<250, 128, 0, s3>>>(S0, N_NODES, C0, 32, pc1, 0);
    k_preduce<<<4, 128, 0, s3>>>(pc1, 0, 250, C0, N_NODES, cs0, 0);
    cudaEventRecord(evCs0, s3);

    // ============ chain A continues (stream 0) ============
    cudaStreamWaitEvent(0, evCorr0, 0);
    k_tn_mma<<<dim3(7, ZSPLIT), 256>>>(S0, xcov, corr0, tnp, tnp2);
    cudaStreamWaitEvent(0, evCs0, 0);
    k_tn_red2<<<(C0 * FDIM + 255) / 256, 256>>>(tnp, tnp2, ZSPLIT, C0, FDIM, cs0,
                                                xc1, T0, csB, qB);

    k_corr<<<C0, 128>>>(xc1, C0, csB, qB, corr1, T0, G0, 1);

    // level 1 cluster
    k_nn_mma3<<<dim3(4, 2), 256, NN3_SMEM>>>(C0, FDIM, xc1, c1W1, c1b1, hA, 1, 0);
    k_nn_mma3<<<dim3(4, 1), 256, NN3_SMEM>>>(C0, C1, hA, c1W2, c1b2, S1, 0, 0);
    k_softmax20<<<50, 256>>>(S1, cs1);
    cudaEventRecord(evS1, 0);

    // ============ chain C part 3 (s3): P1 = S0 @ S1 ============
    cudaStreamWaitEvent(s3, evS1, 0);
    k_gemm_nn<<<dim3(125, 1), 256, 0, s3>>>(N_NODES, C1, C0, S0, S1, 0, P1, 0, 0);
    cudaEventRecord(evP1, s3);

    // ============ chain A tail (stream 0): fused level-1 TN ============
    k_tn16<<<C1, 128>>>(S1, xc1, corr1, cs1, xc2, T1, csC, qC);
    k_corr<<<C1, 128>>>(xc2, C1, csC, qC, corr2, T1, G1, 1);

    cudaStreamWaitEvent(0, evP1, 0);
    k_fused_mask<<<EDGES / 128, 256, FUSED_SMEM>>>(S0, G0, P1, G1, er, ec, adjv, outAdj);

    // ============ join ============
    cudaEventRecord(evJoin, s2);
    cudaStreamWaitEvent(0, evJoin, 0);

    cudaEventDestroy(evFork);
    cudaEventDestroy(evJoin);
    cudaEventDestroy(evCorr0);
    cudaEventDestroy(evS0);
    cudaEventDestroy(evCs0);
    cudaEventDestroy(evS1);
    cudaEventDestroy(evP1);
    cudaStreamDestroy(s2);
    cudaStreamDestroy(s3);

    (void)in_sizes; (void)n_in; (void)out_size;
}